// round 12
// baseline (speedup 1.0000x reference)
#include <cuda_runtime.h>
#include <cuda_fp16.h>

#define NN 100000
#define EE 1600000
#define NCHUNK 128
#define CH 782   // ceil(100000/128)

// ---------------- scratch (static device globals) ----------------------------
__device__ unsigned int g_hp1h[NN * 32];   // half2 bit patterns, 64ch/node
__device__ float g_out1[NN * 64];
__device__ float g_as1[NN * 4];
__device__ float g_ad1[NN * 4];
__device__ float g_asum1[NN * 4];
__device__ unsigned int g_hp2h[NN * 32];
__device__ float g_out2[NN * 64];
__device__ float g_as2[NN];
__device__ float g_ad2[NN];
__device__ float g_asum2[NN];
__device__ unsigned int g_EAh[NN * 32];    // fp16 EA
__device__ float g_EB[NN * 64];
// CSR build
__device__ int  g_cnt[NN];                 // zero on entry; re-zeroed in k_scanwrite
__device__ int  g_offs[NN + 1];
__device__ int  g_cur[NN];
__device__ int4 g_csr4[EE];                // (src, eid, eattr0_bits, eattr1_bits)
__device__ int  g_boff[NCHUNK];

// ---------------- helpers ----------------------------------------------------
__device__ __forceinline__ float lrelu(float x, float s) { return x > 0.f ? x : s * x; }
__device__ __forceinline__ float tanha(float x) {
    float r; asm("tanh.approx.f32 %0, %1;" : "=f"(r) : "f"(x)); return r;
}

typedef unsigned long long ull;
__device__ __forceinline__ ull pack2(float v) {
    ull r;
    unsigned int u = __float_as_uint(v);
    asm("mov.b64 %0, {%1, %1};" : "=l"(r) : "r"(u));
    return r;
}
__device__ __forceinline__ void fma2(ull& d, ull a, ull b) {
    asm("fma.rn.f32x2 %0, %1, %2, %3;" : "=l"(d) : "l"(a), "l"(b), "l"(d));
}
__device__ __forceinline__ float2 unpack2(ull v) {
    unsigned int lo, hi;
    asm("mov.b64 {%0, %1}, %2;" : "=r"(lo), "=r"(hi) : "l"(v));
    return make_float2(__uint_as_float(lo), __uint_as_float(hi));
}
__device__ __forceinline__ unsigned int h2bits(float a, float b) {
    __half2 h = __floats2half2_rn(a, b);
    return *(unsigned int*)&h;
}
__device__ __forceinline__ float2 h2f2(unsigned int b) {
    return __half22float2(*(__half2*)&b);
}

// ==================== CSR build ==============================================
__global__ void k_hist(const int* __restrict__ dst, int e) {
    int t = blockIdx.x * blockDim.x + threadIdx.x;
    if (t < e) atomicAdd(&g_cnt[dst[t]], 1);
}
__global__ void k_sumscan(int n) {
    __shared__ int ssum[NCHUNK];
    int t = threadIdx.x;                   // 1024
    int chunk = t >> 3, sub = t & 7;
    int base = chunk * CH;
    int s = 0;
    for (int i = sub; i < CH; i += 8) {
        int idx = base + i;
        if (idx < n) s += g_cnt[idx];
    }
    s += __shfl_xor_sync(0xffffffffu, s, 1);
    s += __shfl_xor_sync(0xffffffffu, s, 2);
    s += __shfl_xor_sync(0xffffffffu, s, 4);
    if (sub == 0) ssum[chunk] = s;
    __syncthreads();
    int tot = (t < NCHUNK) ? ssum[t] : 0;
    for (int o = 1; o < NCHUNK; o <<= 1) {
        int x = (t < NCHUNK && t >= o) ? ssum[t - o] : 0;
        __syncthreads();
        if (t < NCHUNK) ssum[t] += x;
        __syncthreads();
    }
    if (t < NCHUNK) g_boff[t] = ssum[t] - tot;   // exclusive
}
__global__ void k_scanwrite(int n) {
    __shared__ int sd[1024];
    int b = blockIdx.x, t = threadIdx.x;
    int base = b * CH;
    int v = (t < CH && base + t < n) ? g_cnt[base + t] : 0;
    sd[t] = v; __syncthreads();
    for (int o = 1; o < 1024; o <<= 1) {
        int x = (t >= o) ? sd[t - o] : 0;
        __syncthreads();
        sd[t] += x;
        __syncthreads();
    }
    int excl = sd[t] - v + g_boff[b];
    if (t < CH && base + t < n) {
        g_offs[base + t] = excl;
        g_cur[base + t] = excl;
        g_cnt[base + t] = 0;               // re-zero for next graph replay
    }
    if (base + t == n - 1) g_offs[n] = excl + v;
}
__global__ void k_scatter(const int* __restrict__ src, const int* __restrict__ dst,
                          const float* __restrict__ eattr, int e) {
    int t = blockIdx.x * blockDim.x + threadIdx.x;
    if (t >= e) return;
    int d = dst[t];
    float2 ea = *(const float2*)&eattr[t * 2];
    int pos = atomicAdd(&g_cur[d], 1);
    g_csr4[pos] = make_int4(src[t], t, __float_as_int(ea.x), __float_as_int(ea.y));
}

// ==================== kernel: encoder+gat1 projection (rank-2, inline pre) ===
__global__ void k_enc_gat1(const float* __restrict__ x,
                           const float* __restrict__ encW, const float* __restrict__ encb,
                           const float* __restrict__ g1W,
                           const float* __restrict__ g1as, const float* __restrict__ g1ad,
                           int n) {
    __shared__ __align__(16) float sP0[64], sP1[64], sPb[64], sAs[64], sAd[64];
    if (threadIdx.x < 64) {
        int c = threadIdx.x;
        float p0 = 0.f, p1 = 0.f, pb = 0.f;
#pragma unroll 8
        for (int k = 0; k < 64; k++) {
            float w = g1W[k * 64 + c];
            p0 = fmaf(encW[k], w, p0);
            p1 = fmaf(encW[64 + k], w, p1);
            pb = fmaf(encb[k], w, pb);
        }
        sP0[c] = p0; sP1[c] = p1; sPb[c] = pb;
        sAs[c] = g1as[c];
        sAd[c] = g1ad[c];
    }
    __syncthreads();
    int node = blockIdx.x * blockDim.x + threadIdx.x;
    if (node >= n) return;

    float2 xv = *(const float2*)&x[node * 2];
    float hp[64];
    float asv[4] = {0, 0, 0, 0}, adv[4] = {0, 0, 0, 0};
#pragma unroll
    for (int c = 0; c < 64; c++) {
        float v = fmaf(xv.x, sP0[c], fmaf(xv.y, sP1[c], sPb[c]));
        hp[c] = v;
        asv[c >> 4] = fmaf(v, sAs[c], asv[c >> 4]);
        adv[c >> 4] = fmaf(v, sAd[c], adv[c >> 4]);
    }
    float es[4];
#pragma unroll
    for (int h = 0; h < 4; h++) {
        g_as1[node * 4 + h] = asv[h];
        g_ad1[node * 4 + h] = adv[h];
        es[h] = __expf(lrelu(asv[h] + adv[h], 0.2f));
    }
    *(float4*)&g_asum1[node * 4] = make_float4(es[0], es[1], es[2], es[3]);
#pragma unroll
    for (int q = 0; q < 8; q++) {
        int c = q * 8;
        uint4 u = make_uint4(h2bits(hp[c], hp[c + 1]), h2bits(hp[c + 2], hp[c + 3]),
                             h2bits(hp[c + 4], hp[c + 5]), h2bits(hp[c + 6], hp[c + 7]));
        *(uint4*)&g_hp1h[node * 32 + q * 4] = u;
        float e0 = es[c >> 4];
        *(float4*)&g_out1[node * 64 + c] =
            make_float4(hp[c] * e0, hp[c + 1] * e0, hp[c + 2] * e0, hp[c + 3] * e0);
        *(float4*)&g_out1[node * 64 + c + 4] =
            make_float4(hp[c + 4] * e0, hp[c + 5] * e0, hp[c + 6] * e0, hp[c + 7] * e0);
    }
}

// ==================== kernel: gat1 gather (warp/node, 2-stage pipeline) ======
__global__ void k_msg1(int n) {
    int warp = (blockIdx.x * blockDim.x + threadIdx.x) >> 5;
    if (warp >= n) return;
    int node = warp;
    int lane = threadIdx.x & 31;
    int beg = g_offs[node], end = g_offs[node + 1];
    int deg = end - beg;
    if (deg <= 0) return;                      // self term already seeded
    int h = lane & 3, eslot = lane >> 2;

    float adh = g_ad1[node * 4 + h];
    float2 acc = *(const float2*)&g_out1[node * 64 + lane * 2];
    float wsum = 0.f;
    int nstrips = (deg + 7) >> 3;
    int4 pad = make_int4(node, 0, 0, 0);

    // prologue: strips 0 and 1 csr; strip 0 alpha+features
    int idxA = beg + eslot;
    int4 ceA = (idxA < end) ? g_csr4[idxA] : pad;
    int idxB = beg + 8 + eslot;
    int4 ceB = (idxB < end) ? g_csr4[idxB] : pad;
    float avA = g_as1[ceA.x * 4 + h];
    float2 vvA[8];
    {
        int ss[8];
#pragma unroll
        for (int k = 0; k < 8; k++) ss[k] = __shfl_sync(0xffffffffu, ceA.x, k * 4);
#pragma unroll
        for (int k = 0; k < 8; k++) vvA[k] = h2f2(g_hp1h[ss[k] * 32 + lane]);
    }

    for (int s = 0; s < nstrips; s++) {
        // stage: issue csr(s+2)
        int4 ceC = pad;
        if (s + 2 < nstrips) {
            int idx = beg + (s + 2) * 8 + eslot;
            ceC = (idx < end) ? g_csr4[idx] : pad;
        }
        // stage: issue alpha(s+1) + features(s+1) via ceB (arrived)
        float avB = 0.f;
        float2 vvB[8];
        if (s + 1 < nstrips) {
            avB = g_as1[ceB.x * 4 + h];
            int ss[8];
#pragma unroll
            for (int k = 0; k < 8; k++) ss[k] = __shfl_sync(0xffffffffu, ceB.x, k * 4);
#pragma unroll
            for (int k = 0; k < 8; k++) vvB[k] = h2f2(g_hp1h[ss[k] * 32 + lane]);
        }
        // process strip s
        bool valid = (beg + s * 8 + eslot) < end;
        float w8 = valid ? __expf(lrelu(avA + adh, 0.2f)) : 0.f;
        wsum += w8;
#pragma unroll
        for (int k = 0; k < 8; k++) {
            float wl = __shfl_sync(0xffffffffu, w8, k * 4 + (lane >> 3));
            acc.x = fmaf(wl, vvA[k].x, acc.x);
            acc.y = fmaf(wl, vvA[k].y, acc.y);
        }
        // rotate
        ceA = ceB; ceB = ceC; avA = avB;
#pragma unroll
        for (int k = 0; k < 8; k++) vvA[k] = vvB[k];
    }
    *(float2*)&g_out1[node * 64 + lane * 2] = acc;
    wsum += __shfl_xor_sync(0xffffffffu, wsum, 4);
    wsum += __shfl_xor_sync(0xffffffffu, wsum, 8);
    wsum += __shfl_xor_sync(0xffffffffu, wsum, 16);
    if (lane < 4) g_asum1[node * 4 + lane] += wsum;
}

// ==================== kernel: finish gat1 + gat2 projection (FFMA2) ==========
__global__ void k_fin1_gat2(const float* __restrict__ g1b,
                            const float* __restrict__ g2W,
                            const float* __restrict__ g2as, const float* __restrict__ g2ad,
                            int n) {
    __shared__ __align__(16) float sW[64 * 64];
    __shared__ __align__(16) float sB[64], sAs[64], sAd[64];
    for (int i = threadIdx.x; i < 4096; i += blockDim.x) sW[i] = g2W[i];
    if (threadIdx.x < 64) {
        sB[threadIdx.x] = g1b[threadIdx.x];
        sAs[threadIdx.x] = g2as[threadIdx.x];
        sAd[threadIdx.x] = g2ad[threadIdx.x];
    }
    __syncthreads();
    int node = blockIdx.x * blockDim.x + threadIdx.x;
    if (node >= n) return;

    float inv[4];
#pragma unroll
    for (int h = 0; h < 4; h++) inv[h] = 1.0f / g_asum1[node * 4 + h];

    ull acc[32];
#pragma unroll
    for (int i = 0; i < 32; i++) acc[i] = 0ULL;
#pragma unroll 2
    for (int k4 = 0; k4 < 16; k4++) {
        float4 o = *(const float4*)&g_out1[node * 64 + k4 * 4];
        float iv = inv[k4 >> 2];
        float hv4[4];
        hv4[0] = o.x * iv + sB[k4 * 4];
        hv4[1] = o.y * iv + sB[k4 * 4 + 1];
        hv4[2] = o.z * iv + sB[k4 * 4 + 2];
        hv4[3] = o.w * iv + sB[k4 * 4 + 3];
#pragma unroll
        for (int j = 0; j < 4; j++) {
            float hj = hv4[j] > 0.f ? hv4[j] : expm1f(hv4[j]);
            ull hv = pack2(hj);
            const ulonglong2* wr = (const ulonglong2*)&sW[(k4 * 4 + j) * 64];
#pragma unroll
            for (int c8 = 0; c8 < 16; c8++) {
                ulonglong2 w = wr[c8];
                fma2(acc[2 * c8], hv, w.x);
                fma2(acc[2 * c8 + 1], hv, w.y);
            }
        }
    }
    float hp[64];
#pragma unroll
    for (int i = 0; i < 32; i++) {
        float2 f = unpack2(acc[i]);
        hp[2 * i] = f.x; hp[2 * i + 1] = f.y;
    }
    float as = 0.f, ad = 0.f;
#pragma unroll
    for (int c = 0; c < 64; c++) {
        as = fmaf(hp[c], sAs[c], as);
        ad = fmaf(hp[c], sAd[c], ad);
    }
    g_as2[node] = as;
    g_ad2[node] = ad;
    float es = __expf(lrelu(as + ad, 0.2f));
    g_asum2[node] = es;
#pragma unroll
    for (int q = 0; q < 8; q++) {
        int c = q * 8;
        uint4 u = make_uint4(h2bits(hp[c], hp[c + 1]), h2bits(hp[c + 2], hp[c + 3]),
                             h2bits(hp[c + 4], hp[c + 5]), h2bits(hp[c + 6], hp[c + 7]));
        *(uint4*)&g_hp2h[node * 32 + q * 4] = u;
        *(float4*)&g_out2[node * 64 + c] =
            make_float4(hp[c] * es, hp[c + 1] * es, hp[c + 2] * es, hp[c + 3] * es);
        *(float4*)&g_out2[node * 64 + c + 4] =
            make_float4(hp[c + 4] * es, hp[c + 5] * es, hp[c + 6] * es, hp[c + 7] * es);
    }
}

// ==================== kernel: gat2 gather (warp/node, 2-stage pipeline) ======
__global__ void k_msg2(int n) {
    int warp = (blockIdx.x * blockDim.x + threadIdx.x) >> 5;
    if (warp >= n) return;
    int node = warp;
    int lane = threadIdx.x & 31;
    int beg = g_offs[node], end = g_offs[node + 1];
    int deg = end - beg;
    if (deg <= 0) return;
    int h = lane & 3, eslot = lane >> 2;

    float ad2 = g_ad2[node];
    float2 acc = *(const float2*)&g_out2[node * 64 + lane * 2];
    float wsum = 0.f;
    int nstrips = (deg + 7) >> 3;
    int4 pad = make_int4(node, 0, 0, 0);

    int idxA = beg + eslot;
    int4 ceA = (idxA < end) ? g_csr4[idxA] : pad;
    int idxB = beg + 8 + eslot;
    int4 ceB = (idxB < end) ? g_csr4[idxB] : pad;
    float avA = g_as2[ceA.x];
    float2 vvA[8];
    {
        int ss[8];
#pragma unroll
        for (int k = 0; k < 8; k++) ss[k] = __shfl_sync(0xffffffffu, ceA.x, k * 4);
#pragma unroll
        for (int k = 0; k < 8; k++) vvA[k] = h2f2(g_hp2h[ss[k] * 32 + lane]);
    }

    for (int s = 0; s < nstrips; s++) {
        int4 ceC = pad;
        if (s + 2 < nstrips) {
            int idx = beg + (s + 2) * 8 + eslot;
            ceC = (idx < end) ? g_csr4[idx] : pad;
        }
        float avB = 0.f;
        float2 vvB[8];
        if (s + 1 < nstrips) {
            avB = g_as2[ceB.x];
            int ss[8];
#pragma unroll
            for (int k = 0; k < 8; k++) ss[k] = __shfl_sync(0xffffffffu, ceB.x, k * 4);
#pragma unroll
            for (int k = 0; k < 8; k++) vvB[k] = h2f2(g_hp2h[ss[k] * 32 + lane]);
        }
        bool valid = (beg + s * 8 + eslot) < end;
        float w8 = valid ? __expf(lrelu(avA + ad2, 0.2f)) : 0.f;
        if (h == 0) wsum += w8;                 // one count per edge
#pragma unroll
        for (int k = 0; k < 8; k++) {
            float wl = __shfl_sync(0xffffffffu, w8, k * 4);
            acc.x = fmaf(wl, vvA[k].x, acc.x);
            acc.y = fmaf(wl, vvA[k].y, acc.y);
        }
        ceA = ceB; ceB = ceC; avA = avB;
#pragma unroll
        for (int k = 0; k < 8; k++) vvA[k] = vvB[k];
    }
    *(float2*)&g_out2[node * 64 + lane * 2] = acc;
    wsum += __shfl_xor_sync(0xffffffffu, wsum, 4);
    wsum += __shfl_xor_sync(0xffffffffu, wsum, 8);
    wsum += __shfl_xor_sync(0xffffffffu, wsum, 16);
    if (lane == 0) g_asum2[node] += wsum;
}

// ==================== kernel: finish gat2 + EA/EB + node head (FFMA2) ========
__global__ void k_fin2_heads(const float* __restrict__ g2b,
                             const float* __restrict__ eoW1, const float* __restrict__ eob1,
                             const float* __restrict__ noW1, const float* __restrict__ nob1,
                             const float* __restrict__ noW2, const float* __restrict__ nob2,
                             float* __restrict__ out, int n, int e) {
    __shared__ __align__(16) float sWa[64 * 64];
    __shared__ __align__(16) float sWb[64 * 64];
    __shared__ __align__(16) float sWn[64 * 64];
    __shared__ __align__(16) float sB[64], sB1[64], sBn[64], sW2[128];
    for (int i = threadIdx.x; i < 4096; i += blockDim.x) {
        sWa[i] = eoW1[i];
        sWb[i] = eoW1[4096 + i];
        sWn[i] = noW1[i];
    }
    if (threadIdx.x < 64) {
        sB[threadIdx.x]  = g2b[threadIdx.x];
        sB1[threadIdx.x] = eob1[threadIdx.x];
        sBn[threadIdx.x] = nob1[threadIdx.x];
    }
    if (threadIdx.x < 128) sW2[threadIdx.x] = noW2[threadIdx.x];
    __syncthreads();
    int node = blockIdx.x * blockDim.x + threadIdx.x;
    if (node >= n) return;

    float inv = 1.0f / g_asum2[node];
    float h2[64];
#pragma unroll
    for (int c4 = 0; c4 < 16; c4++) {
        float4 o = *(const float4*)&g_out2[node * 64 + c4 * 4];
        h2[c4 * 4]     = o.x * inv + sB[c4 * 4];
        h2[c4 * 4 + 1] = o.y * inv + sB[c4 * 4 + 1];
        h2[c4 * 4 + 2] = o.z * inv + sB[c4 * 4 + 2];
        h2[c4 * 4 + 3] = o.w * inv + sB[c4 * 4 + 3];
    }

    ull acc[32];
    // ---- EA = h2 @ Wa + b1 (fp16 store) ----
#pragma unroll
    for (int i = 0; i < 32; i++) acc[i] = 0ULL;
#pragma unroll 4
    for (int k = 0; k < 64; k++) {
        ull hv = pack2(h2[k]);
        const ulonglong2* wr = (const ulonglong2*)&sWa[k * 64];
#pragma unroll
        for (int c8 = 0; c8 < 16; c8++) {
            ulonglong2 w = wr[c8];
            fma2(acc[2 * c8], hv, w.x);
            fma2(acc[2 * c8 + 1], hv, w.y);
        }
    }
#pragma unroll
    for (int q = 0; q < 8; q++) {
        float2 f0 = unpack2(acc[q * 4]),     f1 = unpack2(acc[q * 4 + 1]);
        float2 f2 = unpack2(acc[q * 4 + 2]), f3 = unpack2(acc[q * 4 + 3]);
        int c = q * 8;
        uint4 u = make_uint4(h2bits(f0.x + sB1[c], f0.y + sB1[c + 1]),
                             h2bits(f1.x + sB1[c + 2], f1.y + sB1[c + 3]),
                             h2bits(f2.x + sB1[c + 4], f2.y + sB1[c + 5]),
                             h2bits(f3.x + sB1[c + 6], f3.y + sB1[c + 7]));
        *(uint4*)&g_EAh[node * 32 + q * 4] = u;
    }
    // ---- EB = h2 @ Wb (fp32) ----
#pragma unroll
    for (int i = 0; i < 32; i++) acc[i] = 0ULL;
#pragma unroll 4
    for (int k = 0; k < 64; k++) {
        ull hv = pack2(h2[k]);
        const ulonglong2* wr = (const ulonglong2*)&sWb[k * 64];
#pragma unroll
        for (int c8 = 0; c8 < 16; c8++) {
            ulonglong2 w = wr[c8];
            fma2(acc[2 * c8], hv, w.x);
            fma2(acc[2 * c8 + 1], hv, w.y);
        }
    }
#pragma unroll
    for (int q = 0; q < 16; q++) {
        float2 f0 = unpack2(acc[q * 2]), f1 = unpack2(acc[q * 2 + 1]);
        *(float4*)&g_EB[node * 64 + q * 4] = make_float4(f0.x, f0.y, f1.x, f1.y);
    }
    // ---- node head ----
#pragma unroll
    for (int i = 0; i < 32; i++) acc[i] = 0ULL;
#pragma unroll 4
    for (int k = 0; k < 64; k++) {
        ull hv = pack2(h2[k]);
        const ulonglong2* wr = (const ulonglong2*)&sWn[k * 64];
#pragma unroll
        for (int c8 = 0; c8 < 16; c8++) {
            ulonglong2 w = wr[c8];
            fma2(acc[2 * c8], hv, w.x);
            fma2(acc[2 * c8 + 1], hv, w.y);
        }
    }
    float p0 = 0.f, p1 = 0.f;
#pragma unroll
    for (int i = 0; i < 32; i++) {
        float2 f = unpack2(acc[i]);
        float t0 = lrelu(f.x + sBn[2 * i], 0.01f);
        float t1 = lrelu(f.y + sBn[2 * i + 1], 0.01f);
        p0 = fmaf(t0, sW2[4 * i],     fmaf(t1, sW2[4 * i + 2], p0));
        p1 = fmaf(t0, sW2[4 * i + 1], fmaf(t1, sW2[4 * i + 3], p1));
    }
    out[e + node * 2]     = tanha(p0 + nob2[0]);
    out[e + node * 2 + 1] = tanha(p1 + nob2[1]);
}

// ==================== kernel: edge head (warp/node, 2-stage pipeline) ========
__global__ void k_edgehead(const float* __restrict__ eoW1,
                           const float* __restrict__ eoW2, const float* __restrict__ eob2,
                           float* __restrict__ out, int n) {
    int warp = (blockIdx.x * blockDim.x + threadIdx.x) >> 5;
    if (warp >= n) return;
    int node = warp;
    int lane = threadIdx.x & 31;
    int beg = g_offs[node], end = g_offs[node + 1];
    int deg = end - beg;
    if (deg <= 0) return;
    int eslot = lane >> 2;

    float2 w128 = *(const float2*)&eoW1[128 * 64 + lane * 2];
    float2 w129 = *(const float2*)&eoW1[129 * 64 + lane * 2];
    float2 w2   = *(const float2*)&eoW2[lane * 2];
    float  b2   = eob2[0];
    float2 eb   = *(const float2*)&g_EB[node * 64 + lane * 2];
    int nstrips = (deg + 7) >> 3;
    int4 pad = make_int4(node, 0, 0, 0);

    int idxA = beg + eslot;
    int4 ceA = (idxA < end) ? g_csr4[idxA] : pad;
    int idxB = beg + 8 + eslot;
    int4 ceB = (idxB < end) ? g_csr4[idxB] : pad;
    float2 vvA[8];
    {
        int ss[8];
#pragma unroll
        for (int k = 0; k < 8; k++) ss[k] = __shfl_sync(0xffffffffu, ceA.x, k * 4);
#pragma unroll
        for (int k = 0; k < 8; k++) vvA[k] = h2f2(g_EAh[ss[k] * 32 + lane]);
    }

    for (int s = 0; s < nstrips; s++) {
        int4 ceC = pad;
        if (s + 2 < nstrips) {
            int idx = beg + (s + 2) * 8 + eslot;
            ceC = (idx < end) ? g_csr4[idx] : pad;
        }
        float2 vvB[8];
        if (s + 1 < nstrips) {
            int ss[8];
#pragma unroll
            for (int k = 0; k < 8; k++) ss[k] = __shfl_sync(0xffffffffu, ceB.x, k * 4);
#pragma unroll
            for (int k = 0; k < 8; k++) vvB[k] = h2f2(g_EAh[ss[k] * 32 + lane]);
        }
        // process strip s: edge attrs live in ceA.z/.w
        float p[8];
#pragma unroll
        for (int k = 0; k < 8; k++) {
            float ex = __shfl_sync(0xffffffffu, __int_as_float(ceA.z), k * 4);
            float ey = __shfl_sync(0xffffffffu, __int_as_float(ceA.w), k * 4);
            float pre0 = vvA[k].x + eb.x + ex * w128.x + ey * w129.x;
            float pre1 = vvA[k].y + eb.y + ex * w128.y + ey * w129.y;
            p[k] = lrelu(pre0, 0.01f) * w2.x + lrelu(pre1, 0.01f) * w2.y;
        }
#pragma unroll
        for (int k = 0; k < 8; k++) {
            p[k] += __shfl_xor_sync(0xffffffffu, p[k], 16);
            p[k] += __shfl_xor_sync(0xffffffffu, p[k], 8);
            p[k] += __shfl_xor_sync(0xffffffffu, p[k], 4);
            p[k] += __shfl_xor_sync(0xffffffffu, p[k], 2);
            p[k] += __shfl_xor_sync(0xffffffffu, p[k], 1);
        }
        int base = beg + s * 8;
#pragma unroll
        for (int k = 0; k < 8; k++) {
            int eid = __shfl_sync(0xffffffffu, ceA.y, k * 4);
            if (lane == 0 && base + k < end) out[eid] = tanha(p[k] + b2);
        }
        ceA = ceB; ceB = ceC;
#pragma unroll
        for (int k = 0; k < 8; k++) vvA[k] = vvB[k];
    }
}

// ==================== launch ==================================================
extern "C" void kernel_launch(void* const* d_in, const int* in_sizes, int n_in,
                              void* d_out, int out_size) {
    const float* x      = (const float*)d_in[0];
    const int*   eidx   = (const int*)d_in[1];
    const float* eattr  = (const float*)d_in[2];
    const float* encW   = (const float*)d_in[3];
    const float* encb   = (const float*)d_in[4];
    const float* g1W    = (const float*)d_in[5];
    const float* g1as   = (const float*)d_in[6];
    const float* g1ad   = (const float*)d_in[7];
    const float* g1b    = (const float*)d_in[8];
    const float* g2W    = (const float*)d_in[9];
    const float* g2as   = (const float*)d_in[10];
    const float* g2ad   = (const float*)d_in[11];
    const float* g2b    = (const float*)d_in[12];
    const float* noW1   = (const float*)d_in[13];
    const float* nob1   = (const float*)d_in[14];
    const float* noW2   = (const float*)d_in[15];
    const float* nob2   = (const float*)d_in[16];
    const float* eoW1   = (const float*)d_in[17];
    const float* eob1   = (const float*)d_in[18];
    const float* eoW2   = (const float*)d_in[19];
    const float* eob2   = (const float*)d_in[20];
    float* out = (float*)d_out;

    int n = in_sizes[0] / 2;
    int e = in_sizes[1] / 2;
    const int* src = eidx;
    const int* dst = eidx + e;

    const int B = 256;
    int gn = (n + B - 1) / B;
    int ge = (e + B - 1) / B;
    int gw = (n * 32 + B - 1) / B;

    // CSR build (dst-sorted) — g_cnt zero on entry, re-zeroed inside k_scanwrite
    k_hist<<<ge, B>>>(dst, e);
    k_sumscan<<<1, 1024>>>(n);
    k_scanwrite<<<NCHUNK, 1024>>>(n);
    k_scatter<<<ge, B>>>(src, dst, eattr, e);

    // pipeline
    k_enc_gat1<<<gn, B>>>(x, encW, encb, g1W, g1as, g1ad, n);
    k_msg1<<<gw, B>>>(n);
    k_fin1_gat2<<<gn, B>>>(g1b, g2W, g2as, g2ad, n);
    k_msg2<<<gw, B>>>(n);
    k_fin2_heads<<<gn, B>>>(g2b, eoW1, eob1, noW1, nob1, noW2, nob2, out, n, e);
    k_edgehead<<<gw, B>>>(eoW1, eoW2, eob2, out, n);
}

// round 13
// speedup vs baseline: 1.0911x; 1.0911x over previous
#include <cuda_runtime.h>
#include <cuda_fp16.h>

#define NN 100000
#define EE 1600000
#define NCHUNK 128
#define CH 782   // ceil(100000/128)

// ---------------- scratch (static device globals) ----------------------------
__device__ unsigned int g_hp1h[NN * 32];   // half2 bit patterns, 64ch/node
__device__ float g_out1[NN * 64];
__device__ float g_as1[NN * 4];
__device__ float g_ad1[NN * 4];
__device__ float g_asum1[NN * 4];
__device__ unsigned int g_hp2h[NN * 32];
__device__ float g_out2[NN * 64];
__device__ float g_as2[NN];
__device__ float g_ad2[NN];
__device__ float g_asum2[NN];
__device__ unsigned int g_EAh[NN * 32];    // fp16 EA
__device__ float g_EB[NN * 64];
// CSR build
__device__ int  g_cnt[NN];                 // zero on entry; re-zeroed in k_scanwrite
__device__ int  g_offs[NN + 1];
__device__ int  g_cur[NN];
__device__ int2 g_csr[EE];                 // .x = src node, .y = edge id
__device__ float2 g_eas[EE];               // eattr sorted by dst (parallel to g_csr)
__device__ int  g_boff[NCHUNK];

// ---------------- helpers ----------------------------------------------------
__device__ __forceinline__ float lrelu(float x, float s) { return x > 0.f ? x : s * x; }
__device__ __forceinline__ float tanha(float x) {
    float r; asm("tanh.approx.f32 %0, %1;" : "=f"(r) : "f"(x)); return r;
}

typedef unsigned long long ull;
__device__ __forceinline__ ull pack2(float v) {
    ull r;
    unsigned int u = __float_as_uint(v);
    asm("mov.b64 %0, {%1, %1};" : "=l"(r) : "r"(u));
    return r;
}
__device__ __forceinline__ void fma2(ull& d, ull a, ull b) {
    asm("fma.rn.f32x2 %0, %1, %2, %3;" : "=l"(d) : "l"(a), "l"(b), "l"(d));
}
__device__ __forceinline__ float2 unpack2(ull v) {
    unsigned int lo, hi;
    asm("mov.b64 {%0, %1}, %2;" : "=r"(lo), "=r"(hi) : "l"(v));
    return make_float2(__uint_as_float(lo), __uint_as_float(hi));
}
__device__ __forceinline__ unsigned int h2bits(float a, float b) {
    __half2 h = __floats2half2_rn(a, b);
    return *(unsigned int*)&h;
}
__device__ __forceinline__ float2 h2f2(unsigned int b) {
    return __half22float2(*(__half2*)&b);
}

// ==================== CSR build ==============================================
__global__ void k_hist(const int* __restrict__ dst, int e) {
    int t = blockIdx.x * blockDim.x + threadIdx.x;
    if (t < e) atomicAdd(&g_cnt[dst[t]], 1);
}
__global__ void k_sumscan(int n) {
    __shared__ int ssum[NCHUNK];
    int t = threadIdx.x;                   // 1024
    int chunk = t >> 3, sub = t & 7;
    int base = chunk * CH;
    int s = 0;
    for (int i = sub; i < CH; i += 8) {
        int idx = base + i;
        if (idx < n) s += g_cnt[idx];
    }
    s += __shfl_xor_sync(0xffffffffu, s, 1);
    s += __shfl_xor_sync(0xffffffffu, s, 2);
    s += __shfl_xor_sync(0xffffffffu, s, 4);
    if (sub == 0) ssum[chunk] = s;
    __syncthreads();
    int tot = (t < NCHUNK) ? ssum[t] : 0;
    for (int o = 1; o < NCHUNK; o <<= 1) {
        int x = (t < NCHUNK && t >= o) ? ssum[t - o] : 0;
        __syncthreads();
        if (t < NCHUNK) ssum[t] += x;
        __syncthreads();
    }
    if (t < NCHUNK) g_boff[t] = ssum[t] - tot;   // exclusive
}
__global__ void k_scanwrite(int n) {
    __shared__ int wsum[32];
    int b = blockIdx.x, t = threadIdx.x;
    int lane = t & 31, wid = t >> 5;
    int base = b * CH;
    int v = (t < CH && base + t < n) ? g_cnt[base + t] : 0;
    // warp-shuffle inclusive scan
    int x = v;
#pragma unroll
    for (int o = 1; o < 32; o <<= 1) {
        int y = __shfl_up_sync(0xffffffffu, x, o);
        if (lane >= o) x += y;
    }
    if (lane == 31) wsum[wid] = x;
    __syncthreads();
    if (wid == 0) {
        int y = wsum[lane];
#pragma unroll
        for (int o = 1; o < 32; o <<= 1) {
            int z = __shfl_up_sync(0xffffffffu, y, o);
            if (lane >= o) y += z;
        }
        wsum[lane] = y;
    }
    __syncthreads();
    int incl = x + (wid > 0 ? wsum[wid - 1] : 0);
    int excl = incl - v + g_boff[b];
    if (t < CH && base + t < n) {
        g_offs[base + t] = excl;
        g_cur[base + t] = excl;
        g_cnt[base + t] = 0;               // re-zero for next graph replay
    }
    if (base + t == n - 1) g_offs[n] = excl + v;
}
__global__ void k_scatter(const int* __restrict__ src, const int* __restrict__ dst,
                          const float* __restrict__ eattr, int e) {
    int t = blockIdx.x * blockDim.x + threadIdx.x;
    if (t >= e) return;
    int d = dst[t];
    float2 ea = *(const float2*)&eattr[t * 2];
    int pos = atomicAdd(&g_cur[d], 1);
    g_csr[pos] = make_int2(src[t], t);
    g_eas[pos] = ea;
}

// ==================== kernel: encoder+gat1 projection (rank-2, inline pre) ===
__global__ void k_enc_gat1(const float* __restrict__ x,
                           const float* __restrict__ encW, const float* __restrict__ encb,
                           const float* __restrict__ g1W,
                           const float* __restrict__ g1as, const float* __restrict__ g1ad,
                           int n) {
    __shared__ __align__(16) float sP0[64], sP1[64], sPb[64], sAs[64], sAd[64];
    if (threadIdx.x < 64) {
        int c = threadIdx.x;
        float p0 = 0.f, p1 = 0.f, pb = 0.f;
#pragma unroll 8
        for (int k = 0; k < 64; k++) {
            float w = g1W[k * 64 + c];
            p0 = fmaf(encW[k], w, p0);
            p1 = fmaf(encW[64 + k], w, p1);
            pb = fmaf(encb[k], w, pb);
        }
        sP0[c] = p0; sP1[c] = p1; sPb[c] = pb;
        sAs[c] = g1as[c];
        sAd[c] = g1ad[c];
    }
    __syncthreads();
    int node = blockIdx.x * blockDim.x + threadIdx.x;
    if (node >= n) return;

    float2 xv = *(const float2*)&x[node * 2];
    float hp[64];
    float asv[4] = {0, 0, 0, 0}, adv[4] = {0, 0, 0, 0};
#pragma unroll
    for (int c = 0; c < 64; c++) {
        float v = fmaf(xv.x, sP0[c], fmaf(xv.y, sP1[c], sPb[c]));
        hp[c] = v;
        asv[c >> 4] = fmaf(v, sAs[c], asv[c >> 4]);
        adv[c >> 4] = fmaf(v, sAd[c], adv[c >> 4]);
    }
    float es[4];
#pragma unroll
    for (int h = 0; h < 4; h++) {
        g_as1[node * 4 + h] = asv[h];
        g_ad1[node * 4 + h] = adv[h];
        es[h] = __expf(lrelu(asv[h] + adv[h], 0.2f));
    }
    *(float4*)&g_asum1[node * 4] = make_float4(es[0], es[1], es[2], es[3]);
#pragma unroll
    for (int q = 0; q < 8; q++) {
        int c = q * 8;
        uint4 u = make_uint4(h2bits(hp[c], hp[c + 1]), h2bits(hp[c + 2], hp[c + 3]),
                             h2bits(hp[c + 4], hp[c + 5]), h2bits(hp[c + 6], hp[c + 7]));
        *(uint4*)&g_hp1h[node * 32 + q * 4] = u;
        float e0 = es[c >> 4];
        *(float4*)&g_out1[node * 64 + c] =
            make_float4(hp[c] * e0, hp[c + 1] * e0, hp[c + 2] * e0, hp[c + 3] * e0);
        *(float4*)&g_out1[node * 64 + c + 4] =
            make_float4(hp[c + 4] * e0, hp[c + 5] * e0, hp[c + 6] * e0, hp[c + 7] * e0);
    }
}

// ==================== kernel: gat1 gather (warp/node, R9 pipelined) ==========
__global__ void k_msg1(int n) {
    int warp = (blockIdx.x * blockDim.x + threadIdx.x) >> 5;
    if (warp >= n) return;
    int node = warp;
    int lane = threadIdx.x & 31;
    int beg = g_offs[node], end = g_offs[node + 1];

    float adh = g_ad1[node * 4 + (lane & 3)];
    float2 acc = *(const float2*)&g_out1[node * 64 + lane * 2];
    float wsum = 0.f;

    int i = beg;
    // prefetch strip 0 (padded)
    int idx0 = i + (lane >> 2);
    int2 ce = (idx0 < end) ? g_csr[idx0] : make_int2(node, 0);
    float av = g_as1[ce.x * 4 + (lane & 3)];

    for (; i + 8 <= end; ) {
        int inext = i + 8;
        int2 ce_n = ce; float av_n = av;
        if (inext < end) {
            int idn = inext + (lane >> 2);
            ce_n = (idn < end) ? g_csr[idn] : make_int2(node, 0);
            av_n = g_as1[ce_n.x * 4 + (lane & 3)];
        }
        float w8 = __expf(lrelu(av + adh, 0.2f));
        wsum += w8;
        int ss[8];
#pragma unroll
        for (int k = 0; k < 8; k++) ss[k] = __shfl_sync(0xffffffffu, ce.x, k * 4);
        float2 vv[8];
#pragma unroll
        for (int k = 0; k < 8; k++) vv[k] = h2f2(g_hp1h[ss[k] * 32 + lane]);
#pragma unroll
        for (int k = 0; k < 8; k++) {
            float wl = __shfl_sync(0xffffffffu, w8, k * 4 + (lane >> 3));
            acc.x = fmaf(wl, vv[k].x, acc.x);
            acc.y = fmaf(wl, vv[k].y, acc.y);
        }
        i = inext;
        ce = ce_n; av = av_n;
    }
    if (i < end) {
        float w8 = (i + (lane >> 2) < end) ? __expf(lrelu(av + adh, 0.2f)) : 0.f;
        wsum += w8;
        int ss[8];
#pragma unroll
        for (int k = 0; k < 8; k++) ss[k] = __shfl_sync(0xffffffffu, ce.x, k * 4);
        float2 vv[8];
#pragma unroll
        for (int k = 0; k < 8; k++) vv[k] = h2f2(g_hp1h[ss[k] * 32 + lane]);
#pragma unroll
        for (int k = 0; k < 8; k++) {
            float wl = __shfl_sync(0xffffffffu, w8, k * 4 + (lane >> 3));
            acc.x = fmaf(wl, vv[k].x, acc.x);
            acc.y = fmaf(wl, vv[k].y, acc.y);
        }
    }
    *(float2*)&g_out1[node * 64 + lane * 2] = acc;
    wsum += __shfl_xor_sync(0xffffffffu, wsum, 4);
    wsum += __shfl_xor_sync(0xffffffffu, wsum, 8);
    wsum += __shfl_xor_sync(0xffffffffu, wsum, 16);
    if (lane < 4) g_asum1[node * 4 + lane] += wsum;
}

// ==================== kernel: finish gat1 + gat2 projection (FFMA2) ==========
__global__ void k_fin1_gat2(const float* __restrict__ g1b,
                            const float* __restrict__ g2W,
                            const float* __restrict__ g2as, const float* __restrict__ g2ad,
                            int n) {
    __shared__ __align__(16) float sW[64 * 64];
    __shared__ __align__(16) float sB[64], sAs[64], sAd[64];
    for (int i = threadIdx.x; i < 4096; i += blockDim.x) sW[i] = g2W[i];
    if (threadIdx.x < 64) {
        sB[threadIdx.x] = g1b[threadIdx.x];
        sAs[threadIdx.x] = g2as[threadIdx.x];
        sAd[threadIdx.x] = g2ad[threadIdx.x];
    }
    __syncthreads();
    int node = blockIdx.x * blockDim.x + threadIdx.x;
    if (node >= n) return;

    float inv[4];
#pragma unroll
    for (int h = 0; h < 4; h++) inv[h] = 1.0f / g_asum1[node * 4 + h];

    ull acc[32];
#pragma unroll
    for (int i = 0; i < 32; i++) acc[i] = 0ULL;
#pragma unroll 2
    for (int k4 = 0; k4 < 16; k4++) {
        float4 o = *(const float4*)&g_out1[node * 64 + k4 * 4];
        float iv = inv[k4 >> 2];
        float hv4[4];
        hv4[0] = o.x * iv + sB[k4 * 4];
        hv4[1] = o.y * iv + sB[k4 * 4 + 1];
        hv4[2] = o.z * iv + sB[k4 * 4 + 2];
        hv4[3] = o.w * iv + sB[k4 * 4 + 3];
#pragma unroll
        for (int j = 0; j < 4; j++) {
            float hj = hv4[j] > 0.f ? hv4[j] : expm1f(hv4[j]);
            ull hv = pack2(hj);
            const ulonglong2* wr = (const ulonglong2*)&sW[(k4 * 4 + j) * 64];
#pragma unroll
            for (int c8 = 0; c8 < 16; c8++) {
                ulonglong2 w = wr[c8];
                fma2(acc[2 * c8], hv, w.x);
                fma2(acc[2 * c8 + 1], hv, w.y);
            }
        }
    }
    float hp[64];
#pragma unroll
    for (int i = 0; i < 32; i++) {
        float2 f = unpack2(acc[i]);
        hp[2 * i] = f.x; hp[2 * i + 1] = f.y;
    }
    float as = 0.f, ad = 0.f;
#pragma unroll
    for (int c = 0; c < 64; c++) {
        as = fmaf(hp[c], sAs[c], as);
        ad = fmaf(hp[c], sAd[c], ad);
    }
    g_as2[node] = as;
    g_ad2[node] = ad;
    float es = __expf(lrelu(as + ad, 0.2f));
    g_asum2[node] = es;
#pragma unroll
    for (int q = 0; q < 8; q++) {
        int c = q * 8;
        uint4 u = make_uint4(h2bits(hp[c], hp[c + 1]), h2bits(hp[c + 2], hp[c + 3]),
                             h2bits(hp[c + 4], hp[c + 5]), h2bits(hp[c + 6], hp[c + 7]));
        *(uint4*)&g_hp2h[node * 32 + q * 4] = u;
        *(float4*)&g_out2[node * 64 + c] =
            make_float4(hp[c] * es, hp[c + 1] * es, hp[c + 2] * es, hp[c + 3] * es);
        *(float4*)&g_out2[node * 64 + c + 4] =
            make_float4(hp[c + 4] * es, hp[c + 5] * es, hp[c + 6] * es, hp[c + 7] * es);
    }
}

// ==================== kernel: gat2 gather (warp/node, R9 pipelined) ==========
__global__ void k_msg2(int n) {
    int warp = (blockIdx.x * blockDim.x + threadIdx.x) >> 5;
    if (warp >= n) return;
    int node = warp;
    int lane = threadIdx.x & 31;
    int beg = g_offs[node], end = g_offs[node + 1];

    float ad2 = g_ad2[node];
    float2 acc = *(const float2*)&g_out2[node * 64 + lane * 2];
    float wsum = 0.f;

    int i = beg;
    int idx0 = i + lane;
    int2 ce = (idx0 < end) ? g_csr[idx0] : make_int2(0, 0);
    float asv = g_as2[ce.x];

    for (; i + 32 <= end; ) {
        int inext = i + 32;
        int2 ce_n = ce; float as_n = asv;
        if (inext < end) {
            int idn = inext + lane;
            ce_n = (idn < end) ? g_csr[idn] : make_int2(0, 0);
            as_n = g_as2[ce_n.x];
        }
        float w32 = __expf(lrelu(asv + ad2, 0.2f));
        wsum += w32;
#pragma unroll
        for (int kk = 0; kk < 4; kk++) {
            int ss[8];
#pragma unroll
            for (int k = 0; k < 8; k++) ss[k] = __shfl_sync(0xffffffffu, ce.x, kk * 8 + k);
            float2 vv[8];
#pragma unroll
            for (int k = 0; k < 8; k++) vv[k] = h2f2(g_hp2h[ss[k] * 32 + lane]);
#pragma unroll
            for (int k = 0; k < 8; k++) {
                float wl = __shfl_sync(0xffffffffu, w32, kk * 8 + k);
                acc.x = fmaf(wl, vv[k].x, acc.x);
                acc.y = fmaf(wl, vv[k].y, acc.y);
            }
        }
        i = inext;
        ce = ce_n; asv = as_n;
    }
    if (i < end) {
        float w32 = (i + lane < end) ? __expf(lrelu(asv + ad2, 0.2f)) : 0.f;
        wsum += w32;
#pragma unroll
        for (int kk = 0; kk < 4; kk++) {
            if (i + kk * 8 >= end) break;
            int ss[8];
#pragma unroll
            for (int k = 0; k < 8; k++) ss[k] = __shfl_sync(0xffffffffu, ce.x, kk * 8 + k);
            float2 vv[8];
#pragma unroll
            for (int k = 0; k < 8; k++) vv[k] = h2f2(g_hp2h[ss[k] * 32 + lane]);
#pragma unroll
            for (int k = 0; k < 8; k++) {
                float wl = __shfl_sync(0xffffffffu, w32, kk * 8 + k);
                acc.x = fmaf(wl, vv[k].x, acc.x);
                acc.y = fmaf(wl, vv[k].y, acc.y);
            }
        }
    }
    *(float2*)&g_out2[node * 64 + lane * 2] = acc;
    wsum += __shfl_xor_sync(0xffffffffu, wsum, 16);
    wsum += __shfl_xor_sync(0xffffffffu, wsum, 8);
    wsum += __shfl_xor_sync(0xffffffffu, wsum, 4);
    wsum += __shfl_xor_sync(0xffffffffu, wsum, 2);
    wsum += __shfl_xor_sync(0xffffffffu, wsum, 1);
    if (lane == 0) g_asum2[node] += wsum;
}

// ==================== kernel: finish gat2 + EA/EB + node head (FFMA2) ========
__global__ void k_fin2_heads(const float* __restrict__ g2b,
                             const float* __restrict__ eoW1, const float* __restrict__ eob1,
                             const float* __restrict__ noW1, const float* __restrict__ nob1,
                             const float* __restrict__ noW2, const float* __restrict__ nob2,
                             float* __restrict__ out, int n, int e) {
    __shared__ __align__(16) float sWa[64 * 64];
    __shared__ __align__(16) float sWb[64 * 64];
    __shared__ __align__(16) float sWn[64 * 64];
    __shared__ __align__(16) float sB[64], sB1[64], sBn[64], sW2[128];
    for (int i = threadIdx.x; i < 4096; i += blockDim.x) {
        sWa[i] = eoW1[i];
        sWb[i] = eoW1[4096 + i];
        sWn[i] = noW1[i];
    }
    if (threadIdx.x < 64) {
        sB[threadIdx.x]  = g2b[threadIdx.x];
        sB1[threadIdx.x] = eob1[threadIdx.x];
        sBn[threadIdx.x] = nob1[threadIdx.x];
    }
    if (threadIdx.x < 128) sW2[threadIdx.x] = noW2[threadIdx.x];
    __syncthreads();
    int node = blockIdx.x * blockDim.x + threadIdx.x;
    if (node >= n) return;

    float inv = 1.0f / g_asum2[node];
    float h2[64];
#pragma unroll
    for (int c4 = 0; c4 < 16; c4++) {
        float4 o = *(const float4*)&g_out2[node * 64 + c4 * 4];
        h2[c4 * 4]     = o.x * inv + sB[c4 * 4];
        h2[c4 * 4 + 1] = o.y * inv + sB[c4 * 4 + 1];
        h2[c4 * 4 + 2] = o.z * inv + sB[c4 * 4 + 2];
        h2[c4 * 4 + 3] = o.w * inv + sB[c4 * 4 + 3];
    }

    ull acc[32];
    // ---- EA = h2 @ Wa + b1 (fp16 store) ----
#pragma unroll
    for (int i = 0; i < 32; i++) acc[i] = 0ULL;
#pragma unroll 4
    for (int k = 0; k < 64; k++) {
        ull hv = pack2(h2[k]);
        const ulonglong2* wr = (const ulonglong2*)&sWa[k * 64];
#pragma unroll
        for (int c8 = 0; c8 < 16; c8++) {
            ulonglong2 w = wr[c8];
            fma2(acc[2 * c8], hv, w.x);
            fma2(acc[2 * c8 + 1], hv, w.y);
        }
    }
#pragma unroll
    for (int q = 0; q < 8; q++) {
        float2 f0 = unpack2(acc[q * 4]),     f1 = unpack2(acc[q * 4 + 1]);
        float2 f2 = unpack2(acc[q * 4 + 2]), f3 = unpack2(acc[q * 4 + 3]);
        int c = q * 8;
        uint4 u = make_uint4(h2bits(f0.x + sB1[c], f0.y + sB1[c + 1]),
                             h2bits(f1.x + sB1[c + 2], f1.y + sB1[c + 3]),
                             h2bits(f2.x + sB1[c + 4], f2.y + sB1[c + 5]),
                             h2bits(f3.x + sB1[c + 6], f3.y + sB1[c + 7]));
        *(uint4*)&g_EAh[node * 32 + q * 4] = u;
    }
    // ---- EB = h2 @ Wb (fp32) ----
#pragma unroll
    for (int i = 0; i < 32; i++) acc[i] = 0ULL;
#pragma unroll 4
    for (int k = 0; k < 64; k++) {
        ull hv = pack2(h2[k]);
        const ulonglong2* wr = (const ulonglong2*)&sWb[k * 64];
#pragma unroll
        for (int c8 = 0; c8 < 16; c8++) {
            ulonglong2 w = wr[c8];
            fma2(acc[2 * c8], hv, w.x);
            fma2(acc[2 * c8 + 1], hv, w.y);
        }
    }
#pragma unroll
    for (int q = 0; q < 16; q++) {
        float2 f0 = unpack2(acc[q * 2]), f1 = unpack2(acc[q * 2 + 1]);
        *(float4*)&g_EB[node * 64 + q * 4] = make_float4(f0.x, f0.y, f1.x, f1.y);
    }
    // ---- node head ----
#pragma unroll
    for (int i = 0; i < 32; i++) acc[i] = 0ULL;
#pragma unroll 4
    for (int k = 0; k < 64; k++) {
        ull hv = pack2(h2[k]);
        const ulonglong2* wr = (const ulonglong2*)&sWn[k * 64];
#pragma unroll
        for (int c8 = 0; c8 < 16; c8++) {
            ulonglong2 w = wr[c8];
            fma2(acc[2 * c8], hv, w.x);
            fma2(acc[2 * c8 + 1], hv, w.y);
        }
    }
    float p0 = 0.f, p1 = 0.f;
#pragma unroll
    for (int i = 0; i < 32; i++) {
        float2 f = unpack2(acc[i]);
        float t0 = lrelu(f.x + sBn[2 * i], 0.01f);
        float t1 = lrelu(f.y + sBn[2 * i + 1], 0.01f);
        p0 = fmaf(t0, sW2[4 * i],     fmaf(t1, sW2[4 * i + 2], p0));
        p1 = fmaf(t0, sW2[4 * i + 1], fmaf(t1, sW2[4 * i + 3], p1));
    }
    out[e + node * 2]     = tanha(p0 + nob2[0]);
    out[e + node * 2 + 1] = tanha(p1 + nob2[1]);
}

// ==================== kernel: edge head (warp/node, R9 + coalesced eattr) ====
__global__ void k_edgehead(const float* __restrict__ eoW1,
                           const float* __restrict__ eoW2, const float* __restrict__ eob2,
                           float* __restrict__ out, int n) {
    int warp = (blockIdx.x * blockDim.x + threadIdx.x) >> 5;
    if (warp >= n) return;
    int node = warp;
    int lane = threadIdx.x & 31;
    int beg = g_offs[node], end = g_offs[node + 1];
    if (beg == end) return;

    float2 w128 = *(const float2*)&eoW1[128 * 64 + lane * 2];
    float2 w129 = *(const float2*)&eoW1[129 * 64 + lane * 2];
    float2 w2   = *(const float2*)&eoW2[lane * 2];
    float  b2   = eob2[0];
    float2 eb   = *(const float2*)&g_EB[node * 64 + lane * 2];

    int i = beg;
    int idx0 = i + lane;
    int2 ce = (idx0 < end) ? g_csr[idx0] : make_int2(0, 0);
    float2 ea = (idx0 < end) ? g_eas[idx0] : make_float2(0.f, 0.f);  // coalesced, independent

    for (; i + 32 <= end; ) {
        int inext = i + 32;
        int2 ce_n = ce; float2 ea_n = ea;
        if (inext < end) {
            int idn = inext + lane;
            ce_n = (idn < end) ? g_csr[idn] : make_int2(0, 0);
            ea_n = (idn < end) ? g_eas[idn] : make_float2(0.f, 0.f);
        }
#pragma unroll
        for (int kk = 0; kk < 4; kk++) {
            int ss[8], ei[8];
            float ex[8], ey[8];
#pragma unroll
            for (int k = 0; k < 8; k++) {
                ss[k] = __shfl_sync(0xffffffffu, ce.x, kk * 8 + k);
                ei[k] = __shfl_sync(0xffffffffu, ce.y, kk * 8 + k);
                ex[k] = __shfl_sync(0xffffffffu, ea.x, kk * 8 + k);
                ey[k] = __shfl_sync(0xffffffffu, ea.y, kk * 8 + k);
            }
            float2 va[8];
#pragma unroll
            for (int k = 0; k < 8; k++) va[k] = h2f2(g_EAh[ss[k] * 32 + lane]);
            float p[8];
#pragma unroll
            for (int k = 0; k < 8; k++) {
                float pre0 = va[k].x + eb.x + ex[k] * w128.x + ey[k] * w129.x;
                float pre1 = va[k].y + eb.y + ex[k] * w128.y + ey[k] * w129.y;
                p[k] = lrelu(pre0, 0.01f) * w2.x + lrelu(pre1, 0.01f) * w2.y;
            }
#pragma unroll
            for (int k = 0; k < 8; k++) {
                p[k] += __shfl_xor_sync(0xffffffffu, p[k], 16);
                p[k] += __shfl_xor_sync(0xffffffffu, p[k], 8);
                p[k] += __shfl_xor_sync(0xffffffffu, p[k], 4);
                p[k] += __shfl_xor_sync(0xffffffffu, p[k], 2);
                p[k] += __shfl_xor_sync(0xffffffffu, p[k], 1);
            }
            // parallel store: lane k (k<8) stores edge k of this subgroup
            float pl = p[0]; int el = ei[0];
#pragma unroll
            for (int k = 1; k < 8; k++)
                if ((lane & 7) == k) { pl = p[k]; el = ei[k]; }
            if (lane < 8) out[el] = tanha(pl + b2);
        }
        i = inext;
        ce = ce_n; ea = ea_n;
    }
    if (i < end) {
#pragma unroll
        for (int kk = 0; kk < 4; kk++) {
            if (i + kk * 8 >= end) break;
            int ss[8], ei[8];
            float ex[8], ey[8];
#pragma unroll
            for (int k = 0; k < 8; k++) {
                ss[k] = __shfl_sync(0xffffffffu, ce.x, kk * 8 + k);
                ei[k] = __shfl_sync(0xffffffffu, ce.y, kk * 8 + k);
                ex[k] = __shfl_sync(0xffffffffu, ea.x, kk * 8 + k);
                ey[k] = __shfl_sync(0xffffffffu, ea.y, kk * 8 + k);
            }
            float2 va[8];
#pragma unroll
            for (int k = 0; k < 8; k++) va[k] = h2f2(g_EAh[ss[k] * 32 + lane]);
            float p[8];
#pragma unroll
            for (int k = 0; k < 8; k++) {
                float pre0 = va[k].x + eb.x + ex[k] * w128.x + ey[k] * w129.x;
                float pre1 = va[k].y + eb.y + ex[k] * w128.y + ey[k] * w129.y;
                p[k] = lrelu(pre0, 0.01f) * w2.x + lrelu(pre1, 0.01f) * w2.y;
            }
#pragma unroll
            for (int k = 0; k < 8; k++) {
                p[k] += __shfl_xor_sync(0xffffffffu, p[k], 16);
                p[k] += __shfl_xor_sync(0xffffffffu, p[k], 8);
                p[k] += __shfl_xor_sync(0xffffffffu, p[k], 4);
                p[k] += __shfl_xor_sync(0xffffffffu, p[k], 2);
                p[k] += __shfl_xor_sync(0xffffffffu, p[k], 1);
            }
            float pl = p[0]; int el = ei[0];
#pragma unroll
            for (int k = 1; k < 8; k++)
                if ((lane & 7) == k) { pl = p[k]; el = ei[k]; }
            if (lane < 8 && (i + kk * 8 + lane) < end) out[el] = tanha(pl + b2);
        }
    }
}

// ==================== launch ==================================================
extern "C" void kernel_launch(void* const* d_in, const int* in_sizes, int n_in,
                              void* d_out, int out_size) {
    const float* x      = (const float*)d_in[0];
    const int*   eidx   = (const int*)d_in[1];
    const float* eattr  = (const float*)d_in[2];
    const float* encW   = (const float*)d_in[3];
    const float* encb   = (const float*)d_in[4];
    const float* g1W    = (const float*)d_in[5];
    const float* g1as   = (const float*)d_in[6];
    const float* g1ad   = (const float*)d_in[7];
    const float* g1b    = (const float*)d_in[8];
    const float* g2W    = (const float*)d_in[9];
    const float* g2as   = (const float*)d_in[10];
    const float* g2ad   = (const float*)d_in[11];
    const float* g2b    = (const float*)d_in[12];
    const float* noW1   = (const float*)d_in[13];
    const float* nob1   = (const float*)d_in[14];
    const float* noW2   = (const float*)d_in[15];
    const float* nob2   = (const float*)d_in[16];
    const float* eoW1   = (const float*)d_in[17];
    const float* eob1   = (const float*)d_in[18];
    const float* eoW2   = (const float*)d_in[19];
    const float* eob2   = (const float*)d_in[20];
    float* out = (float*)d_out;

    int n = in_sizes[0] / 2;
    int e = in_sizes[1] / 2;
    const int* src = eidx;
    const int* dst = eidx + e;

    const int B = 256;
    int gn = (n + B - 1) / B;
    int ge = (e + B - 1) / B;
    int gw = (n * 32 + B - 1) / B;

    // CSR build (dst-sorted) — g_cnt zero on entry, re-zeroed inside k_scanwrite
    k_hist<<<ge, B>>>(dst, e);
    k_sumscan<<<1, 1024>>>(n);
    k_scanwrite<<<NCHUNK, 1024>>>(n);
    k_scatter<<<ge, B>>>(src, dst, eattr, e);

    // pipeline
    k_enc_gat1<<<gn, B>>>(x, encW, encb, g1W, g1as, g1ad, n);
    k_msg1<<<gw, B>>>(n);
    k_fin1_gat2<<<gn, B>>>(g1b, g2W, g2as, g2ad, n);
    k_msg2<<<gw, B>>>(n);
    k_fin2_heads<<<gn, B>>>(g2b, eoW1, eob1, noW1, nob1, noW2, nob2, out, n, e);
    k_edgehead<<<gw, B>>>(eoW1, eoW2, eob2, out, n);
}

// round 15
// speedup vs baseline: 1.1100x; 1.0173x over previous
#include <cuda_runtime.h>
#include <cuda_fp16.h>

#define NN 100000
#define EE 1600000
#define NCHUNK 128
#define CH 782   // ceil(100000/128)

// ---------------- scratch (static device globals) ----------------------------
__device__ unsigned int g_hp1h[NN * 32];   // half2 bit patterns, 64ch/node
__device__ float g_out1[NN * 64];
__device__ float g_as1[NN * 4];
__device__ float g_ad1[NN * 4];
__device__ float g_asum1[NN * 4];
__device__ unsigned int g_hp2h[NN * 32];
__device__ float g_out2[NN * 64];
__device__ float g_as2[NN];
__device__ float g_ad2[NN];
__device__ float g_asum2[NN];
__device__ unsigned int g_EAh[NN * 32];    // fp16 EA
__device__ float g_EB[NN * 64];
// CSR build
__device__ int  g_cnt[NN];                 // zero on entry; re-zeroed in k_scanwrite
__device__ int  g_offs[NN + 1];
__device__ int  g_cur[NN];
__device__ int2 g_csr[EE];                 // .x = src node, .y = edge id
__device__ int  g_boff[NCHUNK];

// ---------------- helpers ----------------------------------------------------
__device__ __forceinline__ float lrelu(float x, float s) { return x > 0.f ? x : s * x; }
__device__ __forceinline__ float tanha(float x) {
    float r; asm("tanh.approx.f32 %0, %1;" : "=f"(r) : "f"(x)); return r;
}

typedef unsigned long long ull;
__device__ __forceinline__ ull pack2(float v) {
    ull r;
    unsigned int u = __float_as_uint(v);
    asm("mov.b64 %0, {%1, %1};" : "=l"(r) : "r"(u));
    return r;
}
__device__ __forceinline__ void fma2(ull& d, ull a, ull b) {
    asm("fma.rn.f32x2 %0, %1, %2, %3;" : "=l"(d) : "l"(a), "l"(b), "l"(d));
}
__device__ __forceinline__ float2 unpack2(ull v) {
    unsigned int lo, hi;
    asm("mov.b64 {%0, %1}, %2;" : "=r"(lo), "=r"(hi) : "l"(v));
    return make_float2(__uint_as_float(lo), __uint_as_float(hi));
}
__device__ __forceinline__ unsigned int h2bits(float a, float b) {
    __half2 h = __floats2half2_rn(a, b);
    return *(unsigned int*)&h;
}
__device__ __forceinline__ float2 h2f2(unsigned int b) {
    return __half22float2(*(__half2*)&b);
}

// ==================== CSR build ==============================================
__global__ void k_hist(const int* __restrict__ dst, int e) {
    int t = blockIdx.x * blockDim.x + threadIdx.x;
    if (t < e) atomicAdd(&g_cnt[dst[t]], 1);
}
__global__ void k_sumscan(int n) {
    __shared__ int ssum[NCHUNK];
    int t = threadIdx.x;                   // 1024
    int chunk = t >> 3, sub = t & 7;
    int base = chunk * CH;
    int s = 0;
    for (int i = sub; i < CH; i += 8) {
        int idx = base + i;
        if (idx < n) s += g_cnt[idx];
    }
    s += __shfl_xor_sync(0xffffffffu, s, 1);
    s += __shfl_xor_sync(0xffffffffu, s, 2);
    s += __shfl_xor_sync(0xffffffffu, s, 4);
    if (sub == 0) ssum[chunk] = s;
    __syncthreads();
    int tot = (t < NCHUNK) ? ssum[t] : 0;
    for (int o = 1; o < NCHUNK; o <<= 1) {
        int x = (t < NCHUNK && t >= o) ? ssum[t - o] : 0;
        __syncthreads();
        if (t < NCHUNK) ssum[t] += x;
        __syncthreads();
    }
    if (t < NCHUNK) g_boff[t] = ssum[t] - tot;   // exclusive
}
__global__ void k_scanwrite(int n) {
    __shared__ int wsum[32];
    int b = blockIdx.x, t = threadIdx.x;
    int lane = t & 31, wid = t >> 5;
    int base = b * CH;
    int v = (t < CH && base + t < n) ? g_cnt[base + t] : 0;
    // warp-shuffle inclusive scan
    int x = v;
#pragma unroll
    for (int o = 1; o < 32; o <<= 1) {
        int y = __shfl_up_sync(0xffffffffu, x, o);
        if (lane >= o) x += y;
    }
    if (lane == 31) wsum[wid] = x;
    __syncthreads();
    if (wid == 0) {
        int y = wsum[lane];
#pragma unroll
        for (int o = 1; o < 32; o <<= 1) {
            int z = __shfl_up_sync(0xffffffffu, y, o);
            if (lane >= o) y += z;
        }
        wsum[lane] = y;
    }
    __syncthreads();
    int incl = x + (wid > 0 ? wsum[wid - 1] : 0);
    int excl = incl - v + g_boff[b];
    if (t < CH && base + t < n) {
        g_offs[base + t] = excl;
        g_cur[base + t] = excl;
        g_cnt[base + t] = 0;               // re-zero for next graph replay
    }
    if (base + t == n - 1) g_offs[n] = excl + v;
}
__global__ void k_scatter(const int* __restrict__ src, const int* __restrict__ dst, int e) {
    int t = blockIdx.x * blockDim.x + threadIdx.x;
    if (t >= e) return;
    int d = dst[t];
    int pos = atomicAdd(&g_cur[d], 1);
    g_csr[pos] = make_int2(src[t], t);
}

// ==================== kernel: encoder+gat1 projection (rank-2, inline pre) ===
__global__ void k_enc_gat1(const float* __restrict__ x,
                           const float* __restrict__ encW, const float* __restrict__ encb,
                           const float* __restrict__ g1W,
                           const float* __restrict__ g1as, const float* __restrict__ g1ad,
                           int n) {
    __shared__ __align__(16) float sP0[64], sP1[64], sPb[64], sAs[64], sAd[64];
    if (threadIdx.x < 64) {
        int c = threadIdx.x;
        float p0 = 0.f, p1 = 0.f, pb = 0.f;
#pragma unroll 8
        for (int k = 0; k < 64; k++) {
            float w = g1W[k * 64 + c];
            p0 = fmaf(encW[k], w, p0);
            p1 = fmaf(encW[64 + k], w, p1);
            pb = fmaf(encb[k], w, pb);
        }
        sP0[c] = p0; sP1[c] = p1; sPb[c] = pb;
        sAs[c] = g1as[c];
        sAd[c] = g1ad[c];
    }
    __syncthreads();
    int node = blockIdx.x * blockDim.x + threadIdx.x;
    if (node >= n) return;

    float2 xv = *(const float2*)&x[node * 2];
    float hp[64];
    float asv[4] = {0, 0, 0, 0}, adv[4] = {0, 0, 0, 0};
#pragma unroll
    for (int c = 0; c < 64; c++) {
        float v = fmaf(xv.x, sP0[c], fmaf(xv.y, sP1[c], sPb[c]));
        hp[c] = v;
        asv[c >> 4] = fmaf(v, sAs[c], asv[c >> 4]);
        adv[c >> 4] = fmaf(v, sAd[c], adv[c >> 4]);
    }
    float es[4];
#pragma unroll
    for (int h = 0; h < 4; h++) {
        g_as1[node * 4 + h] = asv[h];
        g_ad1[node * 4 + h] = adv[h];
        es[h] = __expf(lrelu(asv[h] + adv[h], 0.2f));
    }
    *(float4*)&g_asum1[node * 4] = make_float4(es[0], es[1], es[2], es[3]);
#pragma unroll
    for (int q = 0; q < 8; q++) {
        int c = q * 8;
        uint4 u = make_uint4(h2bits(hp[c], hp[c + 1]), h2bits(hp[c + 2], hp[c + 3]),
                             h2bits(hp[c + 4], hp[c + 5]), h2bits(hp[c + 6], hp[c + 7]));
        *(uint4*)&g_hp1h[node * 32 + q * 4] = u;
        float e0 = es[c >> 4];
        *(float4*)&g_out1[node * 64 + c] =
            make_float4(hp[c] * e0, hp[c + 1] * e0, hp[c + 2] * e0, hp[c + 3] * e0);
        *(float4*)&g_out1[node * 64 + c + 4] =
            make_float4(hp[c + 4] * e0, hp[c + 5] * e0, hp[c + 6] * e0, hp[c + 7] * e0);
    }
}

// ==================== kernel: gat1 gather (warp/node, R9 pipelined) ==========
__global__ void k_msg1(int n) {
    int warp = (blockIdx.x * blockDim.x + threadIdx.x) >> 5;
    if (warp >= n) return;
    int node = warp;
    int lane = threadIdx.x & 31;
    int beg = g_offs[node], end = g_offs[node + 1];

    float adh = g_ad1[node * 4 + (lane & 3)];
    float2 acc = *(const float2*)&g_out1[node * 64 + lane * 2];
    float wsum = 0.f;

    int i = beg;
    // prefetch strip 0 (padded)
    int idx0 = i + (lane >> 2);
    int2 ce = (idx0 < end) ? g_csr[idx0] : make_int2(node, 0);
    float av = g_as1[ce.x * 4 + (lane & 3)];

    for (; i + 8 <= end; ) {
        int inext = i + 8;
        int2 ce_n = ce; float av_n = av;
        if (inext < end) {
            int idn = inext + (lane >> 2);
            ce_n = (idn < end) ? g_csr[idn] : make_int2(node, 0);
            av_n = g_as1[ce_n.x * 4 + (lane & 3)];
        }
        float w8 = __expf(lrelu(av + adh, 0.2f));
        wsum += w8;
        int ss[8];
#pragma unroll
        for (int k = 0; k < 8; k++) ss[k] = __shfl_sync(0xffffffffu, ce.x, k * 4);
        float2 vv[8];
#pragma unroll
        for (int k = 0; k < 8; k++) vv[k] = h2f2(g_hp1h[ss[k] * 32 + lane]);
#pragma unroll
        for (int k = 0; k < 8; k++) {
            float wl = __shfl_sync(0xffffffffu, w8, k * 4 + (lane >> 3));
            acc.x = fmaf(wl, vv[k].x, acc.x);
            acc.y = fmaf(wl, vv[k].y, acc.y);
        }
        i = inext;
        ce = ce_n; av = av_n;
    }
    if (i < end) {
        float w8 = (i + (lane >> 2) < end) ? __expf(lrelu(av + adh, 0.2f)) : 0.f;
        wsum += w8;
        int ss[8];
#pragma unroll
        for (int k = 0; k < 8; k++) ss[k] = __shfl_sync(0xffffffffu, ce.x, k * 4);
        float2 vv[8];
#pragma unroll
        for (int k = 0; k < 8; k++) vv[k] = h2f2(g_hp1h[ss[k] * 32 + lane]);
#pragma unroll
        for (int k = 0; k < 8; k++) {
            float wl = __shfl_sync(0xffffffffu, w8, k * 4 + (lane >> 3));
            acc.x = fmaf(wl, vv[k].x, acc.x);
            acc.y = fmaf(wl, vv[k].y, acc.y);
        }
    }
    *(float2*)&g_out1[node * 64 + lane * 2] = acc;
    wsum += __shfl_xor_sync(0xffffffffu, wsum, 4);
    wsum += __shfl_xor_sync(0xffffffffu, wsum, 8);
    wsum += __shfl_xor_sync(0xffffffffu, wsum, 16);
    if (lane < 4) g_asum1[node * 4 + lane] += wsum;
}

// ==================== kernel: finish gat1 + gat2 projection (FFMA2) ==========
__global__ void k_fin1_gat2(const float* __restrict__ g1b,
                            const float* __restrict__ g2W,
                            const float* __restrict__ g2as, const float* __restrict__ g2ad,
                            int n) {
    __shared__ __align__(16) float sW[64 * 64];
    __shared__ __align__(16) float sB[64], sAs[64], sAd[64];
    for (int i = threadIdx.x; i < 4096; i += blockDim.x) sW[i] = g2W[i];
    if (threadIdx.x < 64) {
        sB[threadIdx.x] = g1b[threadIdx.x];
        sAs[threadIdx.x] = g2as[threadIdx.x];
        sAd[threadIdx.x] = g2ad[threadIdx.x];
    }
    __syncthreads();
    int node = blockIdx.x * blockDim.x + threadIdx.x;
    if (node >= n) return;

    float inv[4];
#pragma unroll
    for (int h = 0; h < 4; h++) inv[h] = 1.0f / g_asum1[node * 4 + h];

    ull acc[32];
#pragma unroll
    for (int i = 0; i < 32; i++) acc[i] = 0ULL;
#pragma unroll 2
    for (int k4 = 0; k4 < 16; k4++) {
        float4 o = *(const float4*)&g_out1[node * 64 + k4 * 4];
        float iv = inv[k4 >> 2];
        float hv4[4];
        hv4[0] = o.x * iv + sB[k4 * 4];
        hv4[1] = o.y * iv + sB[k4 * 4 + 1];
        hv4[2] = o.z * iv + sB[k4 * 4 + 2];
        hv4[3] = o.w * iv + sB[k4 * 4 + 3];
#pragma unroll
        for (int j = 0; j < 4; j++) {
            float hj = hv4[j] > 0.f ? hv4[j] : expm1f(hv4[j]);
            ull hv = pack2(hj);
            const ulonglong2* wr = (const ulonglong2*)&sW[(k4 * 4 + j) * 64];
#pragma unroll
            for (int c8 = 0; c8 < 16; c8++) {
                ulonglong2 w = wr[c8];
                fma2(acc[2 * c8], hv, w.x);
                fma2(acc[2 * c8 + 1], hv, w.y);
            }
        }
    }
    float hp[64];
#pragma unroll
    for (int i = 0; i < 32; i++) {
        float2 f = unpack2(acc[i]);
        hp[2 * i] = f.x; hp[2 * i + 1] = f.y;
    }
    float as = 0.f, ad = 0.f;
#pragma unroll
    for (int c = 0; c < 64; c++) {
        as = fmaf(hp[c], sAs[c], as);
        ad = fmaf(hp[c], sAd[c], ad);
    }
    g_as2[node] = as;
    g_ad2[node] = ad;
    float es = __expf(lrelu(as + ad, 0.2f));
    g_asum2[node] = es;
#pragma unroll
    for (int q = 0; q < 8; q++) {
        int c = q * 8;
        uint4 u = make_uint4(h2bits(hp[c], hp[c + 1]), h2bits(hp[c + 2], hp[c + 3]),
                             h2bits(hp[c + 4], hp[c + 5]), h2bits(hp[c + 6], hp[c + 7]));
        *(uint4*)&g_hp2h[node * 32 + q * 4] = u;
        *(float4*)&g_out2[node * 64 + c] =
            make_float4(hp[c] * es, hp[c + 1] * es, hp[c + 2] * es, hp[c + 3] * es);
        *(float4*)&g_out2[node * 64 + c + 4] =
            make_float4(hp[c + 4] * es, hp[c + 5] * es, hp[c + 6] * es, hp[c + 7] * es);
    }
}

// ==================== kernel: gat2 gather (warp/node, R9 pipelined) ==========
__global__ void k_msg2(int n) {
    int warp = (blockIdx.x * blockDim.x + threadIdx.x) >> 5;
    if (warp >= n) return;
    int node = warp;
    int lane = threadIdx.x & 31;
    int beg = g_offs[node], end = g_offs[node + 1];

    float ad2 = g_ad2[node];
    float2 acc = *(const float2*)&g_out2[node * 64 + lane * 2];
    float wsum = 0.f;

    int i = beg;
    int idx0 = i + lane;
    int2 ce = (idx0 < end) ? g_csr[idx0] : make_int2(0, 0);
    float asv = g_as2[ce.x];

    for (; i + 32 <= end; ) {
        int inext = i + 32;
        int2 ce_n = ce; float as_n = asv;
        if (inext < end) {
            int idn = inext + lane;
            ce_n = (idn < end) ? g_csr[idn] : make_int2(0, 0);
            as_n = g_as2[ce_n.x];
        }
        float w32 = __expf(lrelu(asv + ad2, 0.2f));
        wsum += w32;
#pragma unroll
        for (int kk = 0; kk < 4; kk++) {
            int ss[8];
#pragma unroll
            for (int k = 0; k < 8; k++) ss[k] = __shfl_sync(0xffffffffu, ce.x, kk * 8 + k);
            float2 vv[8];
#pragma unroll
            for (int k = 0; k < 8; k++) vv[k] = h2f2(g_hp2h[ss[k] * 32 + lane]);
#pragma unroll
            for (int k = 0; k < 8; k++) {
                float wl = __shfl_sync(0xffffffffu, w32, kk * 8 + k);
                acc.x = fmaf(wl, vv[k].x, acc.x);
                acc.y = fmaf(wl, vv[k].y, acc.y);
            }
        }
        i = inext;
        ce = ce_n; asv = as_n;
    }
    if (i < end) {
        float w32 = (i + lane < end) ? __expf(lrelu(asv + ad2, 0.2f)) : 0.f;
        wsum += w32;
#pragma unroll
        for (int kk = 0; kk < 4; kk++) {
            if (i + kk * 8 >= end) break;
            int ss[8];
#pragma unroll
            for (int k = 0; k < 8; k++) ss[k] = __shfl_sync(0xffffffffu, ce.x, kk * 8 + k);
            float2 vv[8];
#pragma unroll
            for (int k = 0; k < 8; k++) vv[k] = h2f2(g_hp2h[ss[k] * 32 + lane]);
#pragma unroll
            for (int k = 0; k < 8; k++) {
                float wl = __shfl_sync(0xffffffffu, w32, kk * 8 + k);
                acc.x = fmaf(wl, vv[k].x, acc.x);
                acc.y = fmaf(wl, vv[k].y, acc.y);
            }
        }
    }
    *(float2*)&g_out2[node * 64 + lane * 2] = acc;
    wsum += __shfl_xor_sync(0xffffffffu, wsum, 16);
    wsum += __shfl_xor_sync(0xffffffffu, wsum, 8);
    wsum += __shfl_xor_sync(0xffffffffu, wsum, 4);
    wsum += __shfl_xor_sync(0xffffffffu, wsum, 2);
    wsum += __shfl_xor_sync(0xffffffffu, wsum, 1);
    if (lane == 0) g_asum2[node] += wsum;
}

// ==================== kernel: finish gat2 + EA/EB + node head (FFMA2) ========
__global__ void k_fin2_heads(const float* __restrict__ g2b,
                             const float* __restrict__ eoW1, const float* __restrict__ eob1,
                             const float* __restrict__ noW1, const float* __restrict__ nob1,
                             const float* __restrict__ noW2, const float* __restrict__ nob2,
                             float* __restrict__ out, int n, int e) {
    __shared__ __align__(16) float sWa[64 * 64];
    __shared__ __align__(16) float sWb[64 * 64];
    __shared__ __align__(16) float sWn[64 * 64];
    __shared__ __align__(16) float sB[64], sB1[64], sBn[64], sW2[128];
    for (int i = threadIdx.x; i < 4096; i += blockDim.x) {
        sWa[i] = eoW1[i];
        sWb[i] = eoW1[4096 + i];
        sWn[i] = noW1[i];
    }
    if (threadIdx.x < 64) {
        sB[threadIdx.x]  = g2b[threadIdx.x];
        sB1[threadIdx.x] = eob1[threadIdx.x];
        sBn[threadIdx.x] = nob1[threadIdx.x];
    }
    if (threadIdx.x < 128) sW2[threadIdx.x] = noW2[threadIdx.x];
    __syncthreads();
    int node = blockIdx.x * blockDim.x + threadIdx.x;
    if (node >= n) return;

    float inv = 1.0f / g_asum2[node];
    float h2[64];
#pragma unroll
    for (int c4 = 0; c4 < 16; c4++) {
        float4 o = *(const float4*)&g_out2[node * 64 + c4 * 4];
        h2[c4 * 4]     = o.x * inv + sB[c4 * 4];
        h2[c4 * 4 + 1] = o.y * inv + sB[c4 * 4 + 1];
        h2[c4 * 4 + 2] = o.z * inv + sB[c4 * 4 + 2];
        h2[c4 * 4 + 3] = o.w * inv + sB[c4 * 4 + 3];
    }

    ull acc[32];
    // ---- EA = h2 @ Wa + b1 (fp16 store) ----
#pragma unroll
    for (int i = 0; i < 32; i++) acc[i] = 0ULL;
#pragma unroll 4
    for (int k = 0; k < 64; k++) {
        ull hv = pack2(h2[k]);
        const ulonglong2* wr = (const ulonglong2*)&sWa[k * 64];
#pragma unroll
        for (int c8 = 0; c8 < 16; c8++) {
            ulonglong2 w = wr[c8];
            fma2(acc[2 * c8], hv, w.x);
            fma2(acc[2 * c8 + 1], hv, w.y);
        }
    }
#pragma unroll
    for (int q = 0; q < 8; q++) {
        float2 f0 = unpack2(acc[q * 4]),     f1 = unpack2(acc[q * 4 + 1]);
        float2 f2 = unpack2(acc[q * 4 + 2]), f3 = unpack2(acc[q * 4 + 3]);
        int c = q * 8;
        uint4 u = make_uint4(h2bits(f0.x + sB1[c], f0.y + sB1[c + 1]),
                             h2bits(f1.x + sB1[c + 2], f1.y + sB1[c + 3]),
                             h2bits(f2.x + sB1[c + 4], f2.y + sB1[c + 5]),
                             h2bits(f3.x + sB1[c + 6], f3.y + sB1[c + 7]));
        *(uint4*)&g_EAh[node * 32 + q * 4] = u;
    }
    // ---- EB = h2 @ Wb (fp32) ----
#pragma unroll
    for (int i = 0; i < 32; i++) acc[i] = 0ULL;
#pragma unroll 4
    for (int k = 0; k < 64; k++) {
        ull hv = pack2(h2[k]);
        const ulonglong2* wr = (const ulonglong2*)&sWb[k * 64];
#pragma unroll
        for (int c8 = 0; c8 < 16; c8++) {
            ulonglong2 w = wr[c8];
            fma2(acc[2 * c8], hv, w.x);
            fma2(acc[2 * c8 + 1], hv, w.y);
        }
    }
#pragma unroll
    for (int q = 0; q < 16; q++) {
        float2 f0 = unpack2(acc[q * 2]), f1 = unpack2(acc[q * 2 + 1]);
        *(float4*)&g_EB[node * 64 + q * 4] = make_float4(f0.x, f0.y, f1.x, f1.y);
    }
    // ---- node head ----
#pragma unroll
    for (int i = 0; i < 32; i++) acc[i] = 0ULL;
#pragma unroll 4
    for (int k = 0; k < 64; k++) {
        ull hv = pack2(h2[k]);
        const ulonglong2* wr = (const ulonglong2*)&sWn[k * 64];
#pragma unroll
        for (int c8 = 0; c8 < 16; c8++) {
            ulonglong2 w = wr[c8];
            fma2(acc[2 * c8], hv, w.x);
            fma2(acc[2 * c8 + 1], hv, w.y);
        }
    }
    float p0 = 0.f, p1 = 0.f;
#pragma unroll
    for (int i = 0; i < 32; i++) {
        float2 f = unpack2(acc[i]);
        float t0 = lrelu(f.x + sBn[2 * i], 0.01f);
        float t1 = lrelu(f.y + sBn[2 * i + 1], 0.01f);
        p0 = fmaf(t0, sW2[4 * i],     fmaf(t1, sW2[4 * i + 2], p0));
        p1 = fmaf(t0, sW2[4 * i + 1], fmaf(t1, sW2[4 * i + 3], p1));
    }
    out[e + node * 2]     = tanha(p0 + nob2[0]);
    out[e + node * 2 + 1] = tanha(p1 + nob2[1]);
}

// ==================== kernel: edge head (warp/node, R9 + parallel stores) ====
__global__ void k_edgehead(const float* __restrict__ eattr,
                           const float* __restrict__ eoW1,
                           const float* __restrict__ eoW2, const float* __restrict__ eob2,
                           float* __restrict__ out, int n) {
    int warp = (blockIdx.x * blockDim.x + threadIdx.x) >> 5;
    if (warp >= n) return;
    int node = warp;
    int lane = threadIdx.x & 31;
    int beg = g_offs[node], end = g_offs[node + 1];
    if (beg == end) return;

    float2 w128 = *(const float2*)&eoW1[128 * 64 + lane * 2];
    float2 w129 = *(const float2*)&eoW1[129 * 64 + lane * 2];
    float2 w2   = *(const float2*)&eoW2[lane * 2];
    float  b2   = eob2[0];
    float2 eb   = *(const float2*)&g_EB[node * 64 + lane * 2];

    int i = beg;
    int idx0 = i + lane;
    int2 ce = (idx0 < end) ? g_csr[idx0] : make_int2(0, 0);
    float2 ea = *(const float2*)&eattr[ce.y * 2];

    // full 32-blocks: no predicates, parallel stores
    for (; i + 32 <= end; ) {
        int inext = i + 32;
        int2 ce_n = ce; float2 ea_n = ea;
        if (inext < end) {
            int idn = inext + lane;
            ce_n = (idn < end) ? g_csr[idn] : make_int2(0, 0);
            ea_n = *(const float2*)&eattr[ce_n.y * 2];
        }
#pragma unroll
        for (int kk = 0; kk < 4; kk++) {
            int ss[8], ei[8];
            float ex[8], ey[8];
#pragma unroll
            for (int k = 0; k < 8; k++) {
                ss[k] = __shfl_sync(0xffffffffu, ce.x, kk * 8 + k);
                ei[k] = __shfl_sync(0xffffffffu, ce.y, kk * 8 + k);
                ex[k] = __shfl_sync(0xffffffffu, ea.x, kk * 8 + k);
                ey[k] = __shfl_sync(0xffffffffu, ea.y, kk * 8 + k);
            }
            float2 va[8];
#pragma unroll
            for (int k = 0; k < 8; k++) va[k] = h2f2(g_EAh[ss[k] * 32 + lane]);
            float p[8];
#pragma unroll
            for (int k = 0; k < 8; k++) {
                float pre0 = va[k].x + eb.x + ex[k] * w128.x + ey[k] * w129.x;
                float pre1 = va[k].y + eb.y + ex[k] * w128.y + ey[k] * w129.y;
                p[k] = lrelu(pre0, 0.01f) * w2.x + lrelu(pre1, 0.01f) * w2.y;
            }
#pragma unroll
            for (int k = 0; k < 8; k++) {
                p[k] += __shfl_xor_sync(0xffffffffu, p[k], 16);
                p[k] += __shfl_xor_sync(0xffffffffu, p[k], 8);
                p[k] += __shfl_xor_sync(0xffffffffu, p[k], 4);
                p[k] += __shfl_xor_sync(0xffffffffu, p[k], 2);
                p[k] += __shfl_xor_sync(0xffffffffu, p[k], 1);
            }
            // parallel store: lane k (k<8) stores edge k of this subgroup
            float pl = p[0]; int el = ei[0];
#pragma unroll
            for (int k = 1; k < 8; k++)
                if ((lane & 7) == k) { pl = p[k]; el = ei[k]; }
            if (lane < 8) out[el] = tanha(pl + b2);
        }
        i = inext;
        ce = ce_n; ea = ea_n;
    }
    // partial tail block
    if (i < end) {
#pragma unroll
        for (int kk = 0; kk < 4; kk++) {
            if (i + kk * 8 >= end) break;
            int ss[8], ei[8];
            float ex[8], ey[8];
#pragma unroll
            for (int k = 0; k < 8; k++) {
                ss[k] = __shfl_sync(0xffffffffu, ce.x, kk * 8 + k);
                ei[k] = __shfl_sync(0xffffffffu, ce.y, kk * 8 + k);
                ex[k] = __shfl_sync(0xffffffffu, ea.x, kk * 8 + k);
                ey[k] = __shfl_sync(0xffffffffu, ea.y, kk * 8 + k);
            }
            float2 va[8];
#pragma unroll
            for (int k = 0; k < 8; k++) va[k] = h2f2(g_EAh[ss[k] * 32 + lane]);
            float p[8];
#pragma unroll
            for (int k = 0; k < 8; k++) {
                float pre0 = va[k].x + eb.x + ex[k] * w128.x + ey[k] * w129.x;
                float pre1 = va[k].y + eb.y + ex[k] * w128.y + ey[k] * w129.y;
                p[k] = lrelu(pre0, 0.01f) * w2.x + lrelu(pre1, 0.01f) * w2.y;
            }
#pragma unroll
            for (int k = 0; k < 8; k++) {
                p[k] += __shfl_xor_sync(0xffffffffu, p[k], 16);
                p[k] += __shfl_xor_sync(0xffffffffu, p[k], 8);
                p[k] += __shfl_xor_sync(0xffffffffu, p[k], 4);
                p[k] += __shfl_xor_sync(0xffffffffu, p[k], 2);
                p[k] += __shfl_xor_sync(0xffffffffu, p[k], 1);
            }
            float pl = p[0]; int el = ei[0];
#pragma unroll
            for (int k = 1; k < 8; k++)
                if ((lane & 7) == k) { pl = p[k]; el = ei[k]; }
            if (lane < 8 && (i + kk * 8 + lane) < end) out[el] = tanha(pl + b2);
        }
    }
}

// ==================== launch ==================================================
extern "C" void kernel_launch(void* const* d_in, const int* in_sizes, int n_in,
                              void* d_out, int out_size) {
    const float* x      = (const float*)d_in[0];
    const int*   eidx   = (const int*)d_in[1];
    const float* eattr  = (const float*)d_in[2];
    const float* encW   = (const float*)d_in[3];
    const float* encb   = (const float*)d_in[4];
    const float* g1W    = (const float*)d_in[5];
    const float* g1as   = (const float*)d_in[6];
    const float* g1ad   = (const float*)d_in[7];
    const float* g1b    = (const float*)d_in[8];
    const float* g2W    = (const float*)d_in[9];
    const float* g2as   = (const float*)d_in[10];
    const float* g2ad   = (const float*)d_in[11];
    const float* g2b    = (const float*)d_in[12];
    const float* noW1   = (const float*)d_in[13];
    const float* nob1   = (const float*)d_in[14];
    const float* noW2   = (const float*)d_in[15];
    const float* nob2   = (const float*)d_in[16];
    const float* eoW1   = (const float*)d_in[17];
    const float* eob1   = (const float*)d_in[18];
    const float* eoW2   = (const float*)d_in[19];
    const float* eob2   = (const float*)d_in[20];
    float* out = (float*)d_out;

    int n = in_sizes[0] / 2;
    int e = in_sizes[1] / 2;
    const int* src = eidx;
    const int* dst = eidx + e;

    const int B = 256;
    int gn = (n + B - 1) / B;
    int ge = (e + B - 1) / B;
    int gw = (n * 32 + B - 1) / B;

    // CSR build (dst-sorted) — g_cnt zero on entry, re-zeroed inside k_scanwrite
    k_hist<<<ge, B>>>(dst, e);
    k_sumscan<<<1, 1024>>>(n);
    k_scanwrite<<<NCHUNK, 1024>>>(n);
    k_scatter<<<ge, B>>>(src, dst, e);

    // pipeline
    k_enc_gat1<<<gn, B>>>(x, encW, encb, g1W, g1as, g1ad, n);
    k_msg1<<<gw, B>>>(n);
    k_fin1_gat2<<<gn, B>>>(g1b, g2W, g2as, g2ad, n);
    k_msg2<<<gw, B>>>(n);
    k_fin2_heads<<<gn, B>>>(g2b, eoW1, eob1, noW1, nob1, noW2, nob2, out, n, e);
    k_edgehead<<<gw, B>>>(eattr, eoW1, eoW2, eob2, out, n);
}

// round 16
// speedup vs baseline: 1.1321x; 1.0198x over previous
#include <cuda_runtime.h>
#include <cuda_fp16.h>

#define NN 100000
#define EE 1600000
#define NCHUNK 128
#define CH 782   // ceil(100000/128)

// ---------------- scratch (static device globals) ----------------------------
__device__ unsigned int g_hp1h[NN * 32];   // half2 bit patterns, 64ch/node
__device__ float g_out1[NN * 64];
__device__ float g_as1[NN * 4];
__device__ float g_ad1[NN * 4];
__device__ float g_asum1[NN * 4];
__device__ unsigned int g_hp2h[NN * 32];
__device__ float g_out2[NN * 64];
__device__ float g_as2[NN];
__device__ float g_ad2[NN];
__device__ float g_asum2[NN];
__device__ unsigned int g_EAh[NN * 32];    // fp16 EA
__device__ float g_EB[NN * 64];
// CSR build
__device__ int  g_cnt[NN];                 // zero on entry; re-zeroed in k_scanwrite
__device__ int  g_offs[NN + 1];
__device__ int  g_cur[NN];
__device__ int4 g_csr[EE];                 // (src, eid, as1_h01 fp16x2, as1_h23 fp16x2)
__device__ int  g_boff[NCHUNK];

// ---------------- helpers ----------------------------------------------------
__device__ __forceinline__ float lrelu(float x, float s) { return x > 0.f ? x : s * x; }
__device__ __forceinline__ float tanha(float x) {
    float r; asm("tanh.approx.f32 %0, %1;" : "=f"(r) : "f"(x)); return r;
}

typedef unsigned long long ull;
__device__ __forceinline__ ull pack2(float v) {
    ull r;
    unsigned int u = __float_as_uint(v);
    asm("mov.b64 %0, {%1, %1};" : "=l"(r) : "r"(u));
    return r;
}
__device__ __forceinline__ void fma2(ull& d, ull a, ull b) {
    asm("fma.rn.f32x2 %0, %1, %2, %3;" : "=l"(d) : "l"(a), "l"(b), "l"(d));
}
__device__ __forceinline__ float2 unpack2(ull v) {
    unsigned int lo, hi;
    asm("mov.b64 {%0, %1}, %2;" : "=r"(lo), "=r"(hi) : "l"(v));
    return make_float2(__uint_as_float(lo), __uint_as_float(hi));
}
__device__ __forceinline__ unsigned int h2bits(float a, float b) {
    __half2 h = __floats2half2_rn(a, b);
    return *(unsigned int*)&h;
}
__device__ __forceinline__ float2 h2f2(unsigned int b) {
    return __half22float2(*(__half2*)&b);
}

// ==================== CSR build ==============================================
__global__ void k_hist(const int* __restrict__ dst, int e) {
    int t = blockIdx.x * blockDim.x + threadIdx.x;
    if (t < e) atomicAdd(&g_cnt[dst[t]], 1);
}
__global__ void k_sumscan(int n) {
    __shared__ int ssum[NCHUNK];
    int t = threadIdx.x;                   // 1024
    int chunk = t >> 3, sub = t & 7;
    int base = chunk * CH;
    int s = 0;
    for (int i = sub; i < CH; i += 8) {
        int idx = base + i;
        if (idx < n) s += g_cnt[idx];
    }
    s += __shfl_xor_sync(0xffffffffu, s, 1);
    s += __shfl_xor_sync(0xffffffffu, s, 2);
    s += __shfl_xor_sync(0xffffffffu, s, 4);
    if (sub == 0) ssum[chunk] = s;
    __syncthreads();
    int tot = (t < NCHUNK) ? ssum[t] : 0;
    for (int o = 1; o < NCHUNK; o <<= 1) {
        int x = (t < NCHUNK && t >= o) ? ssum[t - o] : 0;
        __syncthreads();
        if (t < NCHUNK) ssum[t] += x;
        __syncthreads();
    }
    if (t < NCHUNK) g_boff[t] = ssum[t] - tot;   // exclusive
}
__global__ void k_scanwrite(int n) {
    __shared__ int sd[1024];
    int b = blockIdx.x, t = threadIdx.x;
    int base = b * CH;
    int v = (t < CH && base + t < n) ? g_cnt[base + t] : 0;
    sd[t] = v; __syncthreads();
    for (int o = 1; o < 1024; o <<= 1) {
        int x = (t >= o) ? sd[t - o] : 0;
        __syncthreads();
        sd[t] += x;
        __syncthreads();
    }
    int excl = sd[t] - v + g_boff[b];
    if (t < CH && base + t < n) {
        g_offs[base + t] = excl;
        g_cur[base + t] = excl;
        g_cnt[base + t] = 0;               // re-zero for next graph replay
    }
    if (base + t == n - 1) g_offs[n] = excl + v;
}
// scatter runs AFTER k_enc_gat1: packs src's as1 (fp16x4) into the CSR entry
__global__ void k_scatter(const int* __restrict__ src, const int* __restrict__ dst, int e) {
    int t = blockIdx.x * blockDim.x + threadIdx.x;
    if (t >= e) return;
    int s = src[t];
    int d = dst[t];
    float4 a = *(const float4*)&g_as1[s * 4];
    int pos = atomicAdd(&g_cur[d], 1);
    g_csr[pos] = make_int4(s, t, (int)h2bits(a.x, a.y), (int)h2bits(a.z, a.w));
}

// ==================== kernel: encoder+gat1 projection (rank-2, inline pre) ===
__global__ void k_enc_gat1(const float* __restrict__ x,
                           const float* __restrict__ encW, const float* __restrict__ encb,
                           const float* __restrict__ g1W,
                           const float* __restrict__ g1as, const float* __restrict__ g1ad,
                           int n) {
    __shared__ __align__(16) float sP0[64], sP1[64], sPb[64], sAs[64], sAd[64];
    if (threadIdx.x < 64) {
        int c = threadIdx.x;
        float p0 = 0.f, p1 = 0.f, pb = 0.f;
#pragma unroll 8
        for (int k = 0; k < 64; k++) {
            float w = g1W[k * 64 + c];
            p0 = fmaf(encW[k], w, p0);
            p1 = fmaf(encW[64 + k], w, p1);
            pb = fmaf(encb[k], w, pb);
        }
        sP0[c] = p0; sP1[c] = p1; sPb[c] = pb;
        sAs[c] = g1as[c];
        sAd[c] = g1ad[c];
    }
    __syncthreads();
    int node = blockIdx.x * blockDim.x + threadIdx.x;
    if (node >= n) return;

    float2 xv = *(const float2*)&x[node * 2];
    float hp[64];
    float asv[4] = {0, 0, 0, 0}, adv[4] = {0, 0, 0, 0};
#pragma unroll
    for (int c = 0; c < 64; c++) {
        float v = fmaf(xv.x, sP0[c], fmaf(xv.y, sP1[c], sPb[c]));
        hp[c] = v;
        asv[c >> 4] = fmaf(v, sAs[c], asv[c >> 4]);
        adv[c >> 4] = fmaf(v, sAd[c], adv[c >> 4]);
    }
    float es[4];
#pragma unroll
    for (int h = 0; h < 4; h++) {
        g_as1[node * 4 + h] = asv[h];
        g_ad1[node * 4 + h] = adv[h];
        es[h] = __expf(lrelu(asv[h] + adv[h], 0.2f));
    }
    *(float4*)&g_asum1[node * 4] = make_float4(es[0], es[1], es[2], es[3]);
#pragma unroll
    for (int q = 0; q < 8; q++) {
        int c = q * 8;
        uint4 u = make_uint4(h2bits(hp[c], hp[c + 1]), h2bits(hp[c + 2], hp[c + 3]),
                             h2bits(hp[c + 4], hp[c + 5]), h2bits(hp[c + 6], hp[c + 7]));
        *(uint4*)&g_hp1h[node * 32 + q * 4] = u;
        float e0 = es[c >> 4];
        *(float4*)&g_out1[node * 64 + c] =
            make_float4(hp[c] * e0, hp[c + 1] * e0, hp[c + 2] * e0, hp[c + 3] * e0);
        *(float4*)&g_out1[node * 64 + c + 4] =
            make_float4(hp[c + 4] * e0, hp[c + 5] * e0, hp[c + 6] * e0, hp[c + 7] * e0);
    }
}

// ==================== kernel: gat1 gather (R9 shape, alpha from CSR) =========
__global__ void k_msg1(int n) {
    int warp = (blockIdx.x * blockDim.x + threadIdx.x) >> 5;
    if (warp >= n) return;
    int node = warp;
    int lane = threadIdx.x & 31;
    int h = lane & 3;
    int beg = g_offs[node], end = g_offs[node + 1];

    float adh = g_ad1[node * 4 + h];
    float2 acc = *(const float2*)&g_out1[node * 64 + lane * 2];
    float wsum = 0.f;

    int i = beg;
    // prefetch strip 0 (padded; .z/.w=0 -> as=0, weight zeroed by predicate)
    int idx0 = i + (lane >> 2);
    int4 ce = (idx0 < end) ? g_csr[idx0] : make_int4(node, 0, 0, 0);

    for (; i + 8 <= end; ) {
        int inext = i + 8;
        int4 ce_n = ce;
        if (inext < end) {
            int idn = inext + (lane >> 2);
            ce_n = (idn < end) ? g_csr[idn] : make_int4(node, 0, 0, 0);
        }
        // alpha for this lane's head, from the CSR payload (no gather!)
        float2 a01 = h2f2((unsigned int)ce.z);
        float2 a23 = h2f2((unsigned int)ce.w);
        float av = (h < 2) ? ((h & 1) ? a01.y : a01.x) : ((h & 1) ? a23.y : a23.x);
        float w8 = __expf(lrelu(av + adh, 0.2f));
        wsum += w8;
        int ss[8];
#pragma unroll
        for (int k = 0; k < 8; k++) ss[k] = __shfl_sync(0xffffffffu, ce.x, k * 4);
        float2 vv[8];
#pragma unroll
        for (int k = 0; k < 8; k++) vv[k] = h2f2(g_hp1h[ss[k] * 32 + lane]);
#pragma unroll
        for (int k = 0; k < 8; k++) {
            float wl = __shfl_sync(0xffffffffu, w8, k * 4 + (lane >> 3));
            acc.x = fmaf(wl, vv[k].x, acc.x);
            acc.y = fmaf(wl, vv[k].y, acc.y);
        }
        i = inext;
        ce = ce_n;
    }
    if (i < end) {
        float2 a01 = h2f2((unsigned int)ce.z);
        float2 a23 = h2f2((unsigned int)ce.w);
        float av = (h < 2) ? ((h & 1) ? a01.y : a01.x) : ((h & 1) ? a23.y : a23.x);
        float w8 = (i + (lane >> 2) < end) ? __expf(lrelu(av + adh, 0.2f)) : 0.f;
        wsum += w8;
        int ss[8];
#pragma unroll
        for (int k = 0; k < 8; k++) ss[k] = __shfl_sync(0xffffffffu, ce.x, k * 4);
        float2 vv[8];
#pragma unroll
        for (int k = 0; k < 8; k++) vv[k] = h2f2(g_hp1h[ss[k] * 32 + lane]);
#pragma unroll
        for (int k = 0; k < 8; k++) {
            float wl = __shfl_sync(0xffffffffu, w8, k * 4 + (lane >> 3));
            acc.x = fmaf(wl, vv[k].x, acc.x);
            acc.y = fmaf(wl, vv[k].y, acc.y);
        }
    }
    *(float2*)&g_out1[node * 64 + lane * 2] = acc;
    wsum += __shfl_xor_sync(0xffffffffu, wsum, 4);
    wsum += __shfl_xor_sync(0xffffffffu, wsum, 8);
    wsum += __shfl_xor_sync(0xffffffffu, wsum, 16);
    if (lane < 4) g_asum1[node * 4 + lane] += wsum;
}

// ==================== kernel: finish gat1 + gat2 projection (FFMA2) ==========
__global__ void k_fin1_gat2(const float* __restrict__ g1b,
                            const float* __restrict__ g2W,
                            const float* __restrict__ g2as, const float* __restrict__ g2ad,
                            int n) {
    __shared__ __align__(16) float sW[64 * 64];
    __shared__ __align__(16) float sB[64], sAs[64], sAd[64];
    for (int i = threadIdx.x; i < 4096; i += blockDim.x) sW[i] = g2W[i];
    if (threadIdx.x < 64) {
        sB[threadIdx.x] = g1b[threadIdx.x];
        sAs[threadIdx.x] = g2as[threadIdx.x];
        sAd[threadIdx.x] = g2ad[threadIdx.x];
    }
    __syncthreads();
    int node = blockIdx.x * blockDim.x + threadIdx.x;
    if (node >= n) return;

    float inv[4];
#pragma unroll
    for (int h = 0; h < 4; h++) inv[h] = 1.0f / g_asum1[node * 4 + h];

    ull acc[32];
#pragma unroll
    for (int i = 0; i < 32; i++) acc[i] = 0ULL;
#pragma unroll 2
    for (int k4 = 0; k4 < 16; k4++) {
        float4 o = *(const float4*)&g_out1[node * 64 + k4 * 4];
        float iv = inv[k4 >> 2];
        float hv4[4];
        hv4[0] = o.x * iv + sB[k4 * 4];
        hv4[1] = o.y * iv + sB[k4 * 4 + 1];
        hv4[2] = o.z * iv + sB[k4 * 4 + 2];
        hv4[3] = o.w * iv + sB[k4 * 4 + 3];
#pragma unroll
        for (int j = 0; j < 4; j++) {
            float hj = hv4[j] > 0.f ? hv4[j] : expm1f(hv4[j]);
            ull hv = pack2(hj);
            const ulonglong2* wr = (const ulonglong2*)&sW[(k4 * 4 + j) * 64];
#pragma unroll
            for (int c8 = 0; c8 < 16; c8++) {
                ulonglong2 w = wr[c8];
                fma2(acc[2 * c8], hv, w.x);
                fma2(acc[2 * c8 + 1], hv, w.y);
            }
        }
    }
    float hp[64];
#pragma unroll
    for (int i = 0; i < 32; i++) {
        float2 f = unpack2(acc[i]);
        hp[2 * i] = f.x; hp[2 * i + 1] = f.y;
    }
    float as = 0.f, ad = 0.f;
#pragma unroll
    for (int c = 0; c < 64; c++) {
        as = fmaf(hp[c], sAs[c], as);
        ad = fmaf(hp[c], sAd[c], ad);
    }
    g_as2[node] = as;
    g_ad2[node] = ad;
    float es = __expf(lrelu(as + ad, 0.2f));
    g_asum2[node] = es;
#pragma unroll
    for (int q = 0; q < 8; q++) {
        int c = q * 8;
        uint4 u = make_uint4(h2bits(hp[c], hp[c + 1]), h2bits(hp[c + 2], hp[c + 3]),
                             h2bits(hp[c + 4], hp[c + 5]), h2bits(hp[c + 6], hp[c + 7]));
        *(uint4*)&g_hp2h[node * 32 + q * 4] = u;
        *(float4*)&g_out2[node * 64 + c] =
            make_float4(hp[c] * es, hp[c + 1] * es, hp[c + 2] * es, hp[c + 3] * es);
        *(float4*)&g_out2[node * 64 + c + 4] =
            make_float4(hp[c + 4] * es, hp[c + 5] * es, hp[c + 6] * es, hp[c + 7] * es);
    }
}

// ==================== kernel: gat2 gather (warp/node, R9 pipelined) ==========
__global__ void k_msg2(int n) {
    int warp = (blockIdx.x * blockDim.x + threadIdx.x) >> 5;
    if (warp >= n) return;
    int node = warp;
    int lane = threadIdx.x & 31;
    int beg = g_offs[node], end = g_offs[node + 1];

    float ad2 = g_ad2[node];
    float2 acc = *(const float2*)&g_out2[node * 64 + lane * 2];
    float wsum = 0.f;

    int i = beg;
    int idx0 = i + lane;
    int2 ce;
    {
        int4 c4 = (idx0 < end) ? g_csr[idx0] : make_int4(0, 0, 0, 0);
        ce = make_int2(c4.x, c4.y);
    }
    float asv = g_as2[ce.x];

    for (; i + 32 <= end; ) {
        int inext = i + 32;
        int2 ce_n = ce; float as_n = asv;
        if (inext < end) {
            int idn = inext + lane;
            int4 c4 = (idn < end) ? g_csr[idn] : make_int4(0, 0, 0, 0);
            ce_n = make_int2(c4.x, c4.y);
            as_n = g_as2[ce_n.x];
        }
        float w32 = __expf(lrelu(asv + ad2, 0.2f));
        wsum += w32;
#pragma unroll
        for (int kk = 0; kk < 4; kk++) {
            int ss[8];
#pragma unroll
            for (int k = 0; k < 8; k++) ss[k] = __shfl_sync(0xffffffffu, ce.x, kk * 8 + k);
            float2 vv[8];
#pragma unroll
            for (int k = 0; k < 8; k++) vv[k] = h2f2(g_hp2h[ss[k] * 32 + lane]);
#pragma unroll
            for (int k = 0; k < 8; k++) {
                float wl = __shfl_sync(0xffffffffu, w32, kk * 8 + k);
                acc.x = fmaf(wl, vv[k].x, acc.x);
                acc.y = fmaf(wl, vv[k].y, acc.y);
            }
        }
        i = inext;
        ce = ce_n; asv = as_n;
    }
    if (i < end) {
        float w32 = (i + lane < end) ? __expf(lrelu(asv + ad2, 0.2f)) : 0.f;
        wsum += w32;
#pragma unroll
        for (int kk = 0; kk < 4; kk++) {
            if (i + kk * 8 >= end) break;
            int ss[8];
#pragma unroll
            for (int k = 0; k < 8; k++) ss[k] = __shfl_sync(0xffffffffu, ce.x, kk * 8 + k);
            float2 vv[8];
#pragma unroll
            for (int k = 0; k < 8; k++) vv[k] = h2f2(g_hp2h[ss[k] * 32 + lane]);
#pragma unroll
            for (int k = 0; k < 8; k++) {
                float wl = __shfl_sync(0xffffffffu, w32, kk * 8 + k);
                acc.x = fmaf(wl, vv[k].x, acc.x);
                acc.y = fmaf(wl, vv[k].y, acc.y);
            }
        }
    }
    *(float2*)&g_out2[node * 64 + lane * 2] = acc;
    wsum += __shfl_xor_sync(0xffffffffu, wsum, 16);
    wsum += __shfl_xor_sync(0xffffffffu, wsum, 8);
    wsum += __shfl_xor_sync(0xffffffffu, wsum, 4);
    wsum += __shfl_xor_sync(0xffffffffu, wsum, 2);
    wsum += __shfl_xor_sync(0xffffffffu, wsum, 1);
    if (lane == 0) g_asum2[node] += wsum;
}

// ==================== kernel: finish gat2 + EA/EB + node head (FFMA2) ========
__global__ void k_fin2_heads(const float* __restrict__ g2b,
                             const float* __restrict__ eoW1, const float* __restrict__ eob1,
                             const float* __restrict__ noW1, const float* __restrict__ nob1,
                             const float* __restrict__ noW2, const float* __restrict__ nob2,
                             float* __restrict__ out, int n, int e) {
    __shared__ __align__(16) float sWa[64 * 64];
    __shared__ __align__(16) float sWb[64 * 64];
    __shared__ __align__(16) float sWn[64 * 64];
    __shared__ __align__(16) float sB[64], sB1[64], sBn[64], sW2[128];
    for (int i = threadIdx.x; i < 4096; i += blockDim.x) {
        sWa[i] = eoW1[i];
        sWb[i] = eoW1[4096 + i];
        sWn[i] = noW1[i];
    }
    if (threadIdx.x < 64) {
        sB[threadIdx.x]  = g2b[threadIdx.x];
        sB1[threadIdx.x] = eob1[threadIdx.x];
        sBn[threadIdx.x] = nob1[threadIdx.x];
    }
    if (threadIdx.x < 128) sW2[threadIdx.x] = noW2[threadIdx.x];
    __syncthreads();
    int node = blockIdx.x * blockDim.x + threadIdx.x;
    if (node >= n) return;

    float inv = 1.0f / g_asum2[node];
    float h2[64];
#pragma unroll
    for (int c4 = 0; c4 < 16; c4++) {
        float4 o = *(const float4*)&g_out2[node * 64 + c4 * 4];
        h2[c4 * 4]     = o.x * inv + sB[c4 * 4];
        h2[c4 * 4 + 1] = o.y * inv + sB[c4 * 4 + 1];
        h2[c4 * 4 + 2] = o.z * inv + sB[c4 * 4 + 2];
        h2[c4 * 4 + 3] = o.w * inv + sB[c4 * 4 + 3];
    }

    ull acc[32];
    // ---- EA = h2 @ Wa + b1 (fp16 store) ----
#pragma unroll
    for (int i = 0; i < 32; i++) acc[i] = 0ULL;
#pragma unroll 4
    for (int k = 0; k < 64; k++) {
        ull hv = pack2(h2[k]);
        const ulonglong2* wr = (const ulonglong2*)&sWa[k * 64];
#pragma unroll
        for (int c8 = 0; c8 < 16; c8++) {
            ulonglong2 w = wr[c8];
            fma2(acc[2 * c8], hv, w.x);
            fma2(acc[2 * c8 + 1], hv, w.y);
        }
    }
#pragma unroll
    for (int q = 0; q < 8; q++) {
        float2 f0 = unpack2(acc[q * 4]),     f1 = unpack2(acc[q * 4 + 1]);
        float2 f2 = unpack2(acc[q * 4 + 2]), f3 = unpack2(acc[q * 4 + 3]);
        int c = q * 8;
        uint4 u = make_uint4(h2bits(f0.x + sB1[c], f0.y + sB1[c + 1]),
                             h2bits(f1.x + sB1[c + 2], f1.y + sB1[c + 3]),
                             h2bits(f2.x + sB1[c + 4], f2.y + sB1[c + 5]),
                             h2bits(f3.x + sB1[c + 6], f3.y + sB1[c + 7]));
        *(uint4*)&g_EAh[node * 32 + q * 4] = u;
    }
    // ---- EB = h2 @ Wb (fp32) ----
#pragma unroll
    for (int i = 0; i < 32; i++) acc[i] = 0ULL;
#pragma unroll 4
    for (int k = 0; k < 64; k++) {
        ull hv = pack2(h2[k]);
        const ulonglong2* wr = (const ulonglong2*)&sWb[k * 64];
#pragma unroll
        for (int c8 = 0; c8 < 16; c8++) {
            ulonglong2 w = wr[c8];
            fma2(acc[2 * c8], hv, w.x);
            fma2(acc[2 * c8 + 1], hv, w.y);
        }
    }
#pragma unroll
    for (int q = 0; q < 16; q++) {
        float2 f0 = unpack2(acc[q * 2]), f1 = unpack2(acc[q * 2 + 1]);
        *(float4*)&g_EB[node * 64 + q * 4] = make_float4(f0.x, f0.y, f1.x, f1.y);
    }
    // ---- node head ----
#pragma unroll
    for (int i = 0; i < 32; i++) acc[i] = 0ULL;
#pragma unroll 4
    for (int k = 0; k < 64; k++) {
        ull hv = pack2(h2[k]);
        const ulonglong2* wr = (const ulonglong2*)&sWn[k * 64];
#pragma unroll
        for (int c8 = 0; c8 < 16; c8++) {
            ulonglong2 w = wr[c8];
            fma2(acc[2 * c8], hv, w.x);
            fma2(acc[2 * c8 + 1], hv, w.y);
        }
    }
    float p0 = 0.f, p1 = 0.f;
#pragma unroll
    for (int i = 0; i < 32; i++) {
        float2 f = unpack2(acc[i]);
        float t0 = lrelu(f.x + sBn[2 * i], 0.01f);
        float t1 = lrelu(f.y + sBn[2 * i + 1], 0.01f);
        p0 = fmaf(t0, sW2[4 * i],     fmaf(t1, sW2[4 * i + 2], p0));
        p1 = fmaf(t0, sW2[4 * i + 1], fmaf(t1, sW2[4 * i + 3], p1));
    }
    out[e + node * 2]     = tanha(p0 + nob2[0]);
    out[e + node * 2 + 1] = tanha(p1 + nob2[1]);
}

// ==================== kernel: edge head (warp/node, R9 shape) ================
__global__ void k_edgehead(const float* __restrict__ eattr,
                           const float* __restrict__ eoW1,
                           const float* __restrict__ eoW2, const float* __restrict__ eob2,
                           float* __restrict__ out, int n) {
    int warp = (blockIdx.x * blockDim.x + threadIdx.x) >> 5;
    if (warp >= n) return;
    int node = warp;
    int lane = threadIdx.x & 31;
    int beg = g_offs[node], end = g_offs[node + 1];
    if (beg == end) return;

    float2 w128 = *(const float2*)&eoW1[128 * 64 + lane * 2];
    float2 w129 = *(const float2*)&eoW1[129 * 64 + lane * 2];
    float2 w2   = *(const float2*)&eoW2[lane * 2];
    float  b2   = eob2[0];
    float2 eb   = *(const float2*)&g_EB[node * 64 + lane * 2];

    int i = beg;
    int idx0 = i + lane;
    int2 ce;
    {
        int4 c4 = (idx0 < end) ? g_csr[idx0] : make_int4(0, 0, 0, 0);
        ce = make_int2(c4.x, c4.y);
    }
    float2 ea = *(const float2*)&eattr[ce.y * 2];

    for (; i + 32 <= end; ) {
        int inext = i + 32;
        int2 ce_n = ce; float2 ea_n = ea;
        if (inext < end) {
            int idn = inext + lane;
            int4 c4 = (idn < end) ? g_csr[idn] : make_int4(0, 0, 0, 0);
            ce_n = make_int2(c4.x, c4.y);
            ea_n = *(const float2*)&eattr[ce_n.y * 2];
        }
#pragma unroll
        for (int kk = 0; kk < 4; kk++) {
            int ss[8], ei[8];
            float ex[8], ey[8];
#pragma unroll
            for (int k = 0; k < 8; k++) {
                ss[k] = __shfl_sync(0xffffffffu, ce.x, kk * 8 + k);
                ei[k] = __shfl_sync(0xffffffffu, ce.y, kk * 8 + k);
                ex[k] = __shfl_sync(0xffffffffu, ea.x, kk * 8 + k);
                ey[k] = __shfl_sync(0xffffffffu, ea.y, kk * 8 + k);
            }
            float2 va[8];
#pragma unroll
            for (int k = 0; k < 8; k++) va[k] = h2f2(g_EAh[ss[k] * 32 + lane]);
            float p[8];
#pragma unroll
            for (int k = 0; k < 8; k++) {
                float pre0 = va[k].x + eb.x + ex[k] * w128.x + ey[k] * w129.x;
                float pre1 = va[k].y + eb.y + ex[k] * w128.y + ey[k] * w129.y;
                p[k] = lrelu(pre0, 0.01f) * w2.x + lrelu(pre1, 0.01f) * w2.y;
            }
#pragma unroll
            for (int k = 0; k < 8; k++) {
                p[k] += __shfl_xor_sync(0xffffffffu, p[k], 16);
                p[k] += __shfl_xor_sync(0xffffffffu, p[k], 8);
                p[k] += __shfl_xor_sync(0xffffffffu, p[k], 4);
                p[k] += __shfl_xor_sync(0xffffffffu, p[k], 2);
                p[k] += __shfl_xor_sync(0xffffffffu, p[k], 1);
            }
            if (lane == 0) {
#pragma unroll
                for (int k = 0; k < 8; k++) out[ei[k]] = tanha(p[k] + b2);
            }
        }
        i = inext;
        ce = ce_n; ea = ea_n;
    }
    if (i < end) {
#pragma unroll
        for (int kk = 0; kk < 4; kk++) {
            if (i + kk * 8 >= end) break;
            int ss[8], ei[8];
            float ex[8], ey[8];
#pragma unroll
            for (int k = 0; k < 8; k++) {
                ss[k] = __shfl_sync(0xffffffffu, ce.x, kk * 8 + k);
                ei[k] = __shfl_sync(0xffffffffu, ce.y, kk * 8 + k);
                ex[k] = __shfl_sync(0xffffffffu, ea.x, kk * 8 + k);
                ey[k] = __shfl_sync(0xffffffffu, ea.y, kk * 8 + k);
            }
            float2 va[8];
#pragma unroll
            for (int k = 0; k < 8; k++) va[k] = h2f2(g_EAh[ss[k] * 32 + lane]);
            float p[8];
#pragma unroll
            for (int k = 0; k < 8; k++) {
                float pre0 = va[k].x + eb.x + ex[k] * w128.x + ey[k] * w129.x;
                float pre1 = va[k].y + eb.y + ex[k] * w128.y + ey[k] * w129.y;
                p[k] = lrelu(pre0, 0.01f) * w2.x + lrelu(pre1, 0.01f) * w2.y;
            }
#pragma unroll
            for (int k = 0; k < 8; k++) {
                p[k] += __shfl_xor_sync(0xffffffffu, p[k], 16);
                p[k] += __shfl_xor_sync(0xffffffffu, p[k], 8);
                p[k] += __shfl_xor_sync(0xffffffffu, p[k], 4);
                p[k] += __shfl_xor_sync(0xffffffffu, p[k], 2);
                p[k] += __shfl_xor_sync(0xffffffffu, p[k], 1);
            }
#pragma unroll
            for (int k = 0; k < 8; k++)
                if (lane == 0 && (i + kk * 8 + k) < end) out[ei[k]] = tanha(p[k] + b2);
        }
    }
}

// ==================== launch ==================================================
extern "C" void kernel_launch(void* const* d_in, const int* in_sizes, int n_in,
                              void* d_out, int out_size) {
    const float* x      = (const float*)d_in[0];
    const int*   eidx   = (const int*)d_in[1];
    const float* eattr  = (const float*)d_in[2];
    const float* encW   = (const float*)d_in[3];
    const float* encb   = (const float*)d_in[4];
    const float* g1W    = (const float*)d_in[5];
    const float* g1as   = (const float*)d_in[6];
    const float* g1ad   = (const float*)d_in[7];
    const float* g1b    = (const float*)d_in[8];
    const float* g2W    = (const float*)d_in[9];
    const float* g2as   = (const float*)d_in[10];
    const float* g2ad   = (const float*)d_in[11];
    const float* g2b    = (const float*)d_in[12];
    const float* noW1   = (const float*)d_in[13];
    const float* nob1   = (const float*)d_in[14];
    const float* noW2   = (const float*)d_in[15];
    const float* nob2   = (const float*)d_in[16];
    const float* eoW1   = (const float*)d_in[17];
    const float* eob1   = (const float*)d_in[18];
    const float* eoW2   = (const float*)d_in[19];
    const float* eob2   = (const float*)d_in[20];
    float* out = (float*)d_out;

    int n = in_sizes[0] / 2;
    int e = in_sizes[1] / 2;
    const int* src = eidx;
    const int* dst = eidx + e;

    const int B = 256;
    int gn = (n + B - 1) / B;
    int ge = (e + B - 1) / B;
    int gw = (n * 32 + B - 1) / B;

    // CSR build; scatter moved AFTER enc so it can pack as1 into the entries
    k_hist<<<ge, B>>>(dst, e);
    k_sumscan<<<1, 1024>>>(n);
    k_scanwrite<<<NCHUNK, 1024>>>(n);
    k_enc_gat1<<<gn, B>>>(x, encW, encb, g1W, g1as, g1ad, n);
    k_scatter<<<ge, B>>>(src, dst, e);

    // pipeline
    k_msg1<<<gw, B>>>(n);
    k_fin1_gat2<<<gn, B>>>(g1b, g2W, g2as, g2ad, n);
    k_msg2<<<gw, B>>>(n);
    k_fin2_heads<<<gn, B>>>(g2b, eoW1, eob1, noW1, nob1, noW2, nob2, out, n, e);
    k_edgehead<<<gw, B>>>(eattr, eoW1, eoW2, eob2, out, n);
}

// round 17
// speedup vs baseline: 1.2344x; 1.0904x over previous
#include <cuda_runtime.h>
#include <cuda_fp16.h>

#define NN 100000
#define EE 1600000
#define NCHUNK 128
#define CH 782   // ceil(100000/128)

// ---------------- scratch (static device globals) ----------------------------
__device__ unsigned int g_hp1h[NN * 32];   // half2 bit patterns, 64ch/node
__device__ float g_out1[NN * 64];
__device__ float g_as1[NN * 4];
__device__ float g_ad1[NN * 4];
__device__ float g_asum1[NN * 4];
__device__ unsigned int g_hp2h[NN * 32];
__device__ float g_out2[NN * 64];
__device__ float g_as2[NN];
__device__ float g_ad2[NN];
__device__ float g_asum2[NN];
__device__ unsigned int g_EAh[NN * 32];    // fp16 EA
__device__ float g_EB[NN * 64];
// CSR build
__device__ int  g_cnt[NN];                 // zero on entry; re-zeroed in k_scanwrite
__device__ int  g_offs[NN + 1];
__device__ int  g_cur[NN];
__device__ int2 g_csr[EE];                 // .x = src node, .y = edge id
__device__ int  g_boff[NCHUNK];

// ---------------- helpers ----------------------------------------------------
__device__ __forceinline__ float lrelu(float x, float s) { return x > 0.f ? x : s * x; }
__device__ __forceinline__ float tanha(float x) {
    float r; asm("tanh.approx.f32 %0, %1;" : "=f"(r) : "f"(x)); return r;
}

typedef unsigned long long ull;
__device__ __forceinline__ ull pack2(float v) {
    ull r;
    unsigned int u = __float_as_uint(v);
    asm("mov.b64 %0, {%1, %1};" : "=l"(r) : "r"(u));
    return r;
}
__device__ __forceinline__ void fma2(ull& d, ull a, ull b) {
    asm("fma.rn.f32x2 %0, %1, %2, %3;" : "=l"(d) : "l"(a), "l"(b), "l"(d));
}
__device__ __forceinline__ float2 unpack2(ull v) {
    unsigned int lo, hi;
    asm("mov.b64 {%0, %1}, %2;" : "=r"(lo), "=r"(hi) : "l"(v));
    return make_float2(__uint_as_float(lo), __uint_as_float(hi));
}
__device__ __forceinline__ unsigned int h2bits(float a, float b) {
    __half2 h = __floats2half2_rn(a, b);
    return *(unsigned int*)&h;
}
__device__ __forceinline__ float2 h2f2(unsigned int b) {
    return __half22float2(*(__half2*)&b);
}

// ==================== CSR build ==============================================
__global__ void k_hist(const int* __restrict__ dst, int e) {
    int t = blockIdx.x * blockDim.x + threadIdx.x;
    if (t < e) atomicAdd(&g_cnt[dst[t]], 1);
}
__global__ void k_sumscan(int n) {
    __shared__ int ssum[NCHUNK];
    int t = threadIdx.x;                   // 1024
    int chunk = t >> 3, sub = t & 7;
    int base = chunk * CH;
    int s = 0;
    for (int i = sub; i < CH; i += 8) {
        int idx = base + i;
        if (idx < n) s += g_cnt[idx];
    }
    s += __shfl_xor_sync(0xffffffffu, s, 1);
    s += __shfl_xor_sync(0xffffffffu, s, 2);
    s += __shfl_xor_sync(0xffffffffu, s, 4);
    if (sub == 0) ssum[chunk] = s;
    __syncthreads();
    int tot = (t < NCHUNK) ? ssum[t] : 0;
    for (int o = 1; o < NCHUNK; o <<= 1) {
        int x = (t < NCHUNK && t >= o) ? ssum[t - o] : 0;
        __syncthreads();
        if (t < NCHUNK) ssum[t] += x;
        __syncthreads();
    }
    if (t < NCHUNK) g_boff[t] = ssum[t] - tot;   // exclusive
}
__global__ void k_scanwrite(int n) {
    __shared__ int sd[1024];
    int b = blockIdx.x, t = threadIdx.x;
    int base = b * CH;
    int v = (t < CH && base + t < n) ? g_cnt[base + t] : 0;
    sd[t] = v; __syncthreads();
    for (int o = 1; o < 1024; o <<= 1) {
        int x = (t >= o) ? sd[t - o] : 0;
        __syncthreads();
        sd[t] += x;
        __syncthreads();
    }
    int excl = sd[t] - v + g_boff[b];
    if (t < CH && base + t < n) {
        g_offs[base + t] = excl;
        g_cur[base + t] = excl;
        g_cnt[base + t] = 0;               // re-zero for next graph replay
    }
    if (base + t == n - 1) g_offs[n] = excl + v;
}
__global__ void k_scatter(const int* __restrict__ src, const int* __restrict__ dst, int e) {
    int t = blockIdx.x * blockDim.x + threadIdx.x;
    if (t >= e) return;
    int d = dst[t];
    int pos = atomicAdd(&g_cur[d], 1);
    g_csr[pos] = make_int2(src[t], t);
}

// ==================== kernel: encoder+gat1 projection (chunked, low-reg) =====
__global__ void k_enc_gat1(const float* __restrict__ x,
                           const float* __restrict__ encW, const float* __restrict__ encb,
                           const float* __restrict__ g1W,
                           const float* __restrict__ g1as, const float* __restrict__ g1ad,
                           int n) {
    __shared__ __align__(16) float sP0[64], sP1[64], sPb[64], sAs[64], sAd[64];
    if (threadIdx.x < 64) {
        int c = threadIdx.x;
        float p0 = 0.f, p1 = 0.f, pb = 0.f;
#pragma unroll 8
        for (int k = 0; k < 64; k++) {
            float w = g1W[k * 64 + c];
            p0 = fmaf(encW[k], w, p0);
            p1 = fmaf(encW[64 + k], w, p1);
            pb = fmaf(encb[k], w, pb);
        }
        sP0[c] = p0; sP1[c] = p1; sPb[c] = pb;
        sAs[c] = g1as[c];
        sAd[c] = g1ad[c];
    }
    __syncthreads();
    int node = blockIdx.x * blockDim.x + threadIdx.x;
    if (node >= n) return;

    float2 xv = *(const float2*)&x[node * 2];
    float asv[4] = {0, 0, 0, 0}, adv[4] = {0, 0, 0, 0};
#pragma unroll
    for (int q = 0; q < 8; q++) {           // 8-channel chunks: no hp[64] array
        int c0 = q * 8;
        int head = q >> 1;
        float v[8];
#pragma unroll
        for (int j = 0; j < 8; j++) {
            int c = c0 + j;
            v[j] = fmaf(xv.x, sP0[c], fmaf(xv.y, sP1[c], sPb[c]));
            asv[head] = fmaf(v[j], sAs[c], asv[head]);
            adv[head] = fmaf(v[j], sAd[c], adv[head]);
        }
        uint4 u = make_uint4(h2bits(v[0], v[1]), h2bits(v[2], v[3]),
                             h2bits(v[4], v[5]), h2bits(v[6], v[7]));
        *(uint4*)&g_hp1h[node * 32 + q * 4] = u;
    }
    float es[4];
#pragma unroll
    for (int h = 0; h < 4; h++) {
        g_as1[node * 4 + h] = asv[h];
        g_ad1[node * 4 + h] = adv[h];
        es[h] = __expf(lrelu(asv[h] + adv[h], 0.2f));
    }
    *(float4*)&g_asum1[node * 4] = make_float4(es[0], es[1], es[2], es[3]);
    // NOTE: no g_out1 seed store — msg1 self-seeds from g_hp1h * es
}

// ==================== kernel: gat1 gather (warp/node, R9 pipelined) ==========
__global__ void k_msg1(int n) {
    int warp = (blockIdx.x * blockDim.x + threadIdx.x) >> 5;
    if (warp >= n) return;
    int node = warp;
    int lane = threadIdx.x & 31;
    int beg = g_offs[node], end = g_offs[node + 1];

    float adh = g_ad1[node * 4 + (lane & 3)];
    // self seed from fp16 feature table (asum1 currently holds the self weight)
    float esh = g_asum1[node * 4 + (lane >> 3)];
    float2 hpv = h2f2(g_hp1h[node * 32 + lane]);
    float2 acc = make_float2(hpv.x * esh, hpv.y * esh);
    float wsum = 0.f;

    int i = beg;
    int idx0 = i + (lane >> 2);
    int2 ce = (idx0 < end) ? g_csr[idx0] : make_int2(node, 0);
    float av = g_as1[ce.x * 4 + (lane & 3)];

    for (; i + 8 <= end; ) {
        int inext = i + 8;
        int2 ce_n = ce; float av_n = av;
        if (inext < end) {
            int idn = inext + (lane >> 2);
            ce_n = (idn < end) ? g_csr[idn] : make_int2(node, 0);
            av_n = g_as1[ce_n.x * 4 + (lane & 3)];
        }
        float w8 = __expf(lrelu(av + adh, 0.2f));
        wsum += w8;
        int ss[8];
#pragma unroll
        for (int k = 0; k < 8; k++) ss[k] = __shfl_sync(0xffffffffu, ce.x, k * 4);
        float2 vv[8];
#pragma unroll
        for (int k = 0; k < 8; k++) vv[k] = h2f2(g_hp1h[ss[k] * 32 + lane]);
#pragma unroll
        for (int k = 0; k < 8; k++) {
            float wl = __shfl_sync(0xffffffffu, w8, k * 4 + (lane >> 3));
            acc.x = fmaf(wl, vv[k].x, acc.x);
            acc.y = fmaf(wl, vv[k].y, acc.y);
        }
        i = inext;
        ce = ce_n; av = av_n;
    }
    if (i < end) {
        float w8 = (i + (lane >> 2) < end) ? __expf(lrelu(av + adh, 0.2f)) : 0.f;
        wsum += w8;
        int ss[8];
#pragma unroll
        for (int k = 0; k < 8; k++) ss[k] = __shfl_sync(0xffffffffu, ce.x, k * 4);
        float2 vv[8];
#pragma unroll
        for (int k = 0; k < 8; k++) vv[k] = h2f2(g_hp1h[ss[k] * 32 + lane]);
#pragma unroll
        for (int k = 0; k < 8; k++) {
            float wl = __shfl_sync(0xffffffffu, w8, k * 4 + (lane >> 3));
            acc.x = fmaf(wl, vv[k].x, acc.x);
            acc.y = fmaf(wl, vv[k].y, acc.y);
        }
    }
    *(float2*)&g_out1[node * 64 + lane * 2] = acc;
    wsum += __shfl_xor_sync(0xffffffffu, wsum, 4);
    wsum += __shfl_xor_sync(0xffffffffu, wsum, 8);
    wsum += __shfl_xor_sync(0xffffffffu, wsum, 16);
    if (lane < 4) g_asum1[node * 4 + lane] += wsum;
}

// ==================== kernel: finish gat1 + gat2 projection (FFMA2) ==========
__global__ void k_fin1_gat2(const float* __restrict__ g1b,
                            const float* __restrict__ g2W,
                            const float* __restrict__ g2as, const float* __restrict__ g2ad,
                            int n) {
    __shared__ __align__(16) float sW[64 * 64];
    __shared__ __align__(16) float sB[64], sAs[64], sAd[64];
    for (int i = threadIdx.x; i < 4096; i += blockDim.x) sW[i] = g2W[i];
    if (threadIdx.x < 64) {
        sB[threadIdx.x] = g1b[threadIdx.x];
        sAs[threadIdx.x] = g2as[threadIdx.x];
        sAd[threadIdx.x] = g2ad[threadIdx.x];
    }
    __syncthreads();
    int node = blockIdx.x * blockDim.x + threadIdx.x;
    if (node >= n) return;

    float inv[4];
#pragma unroll
    for (int h = 0; h < 4; h++) inv[h] = 1.0f / g_asum1[node * 4 + h];

    ull acc[32];
#pragma unroll
    for (int i = 0; i < 32; i++) acc[i] = 0ULL;
#pragma unroll 2
    for (int k4 = 0; k4 < 16; k4++) {
        float4 o = *(const float4*)&g_out1[node * 64 + k4 * 4];
        float iv = inv[k4 >> 2];
        float hv4[4];
        hv4[0] = o.x * iv + sB[k4 * 4];
        hv4[1] = o.y * iv + sB[k4 * 4 + 1];
        hv4[2] = o.z * iv + sB[k4 * 4 + 2];
        hv4[3] = o.w * iv + sB[k4 * 4 + 3];
#pragma unroll
        for (int j = 0; j < 4; j++) {
            float hj = hv4[j] > 0.f ? hv4[j] : expm1f(hv4[j]);
            ull hv = pack2(hj);
            const ulonglong2* wr = (const ulonglong2*)&sW[(k4 * 4 + j) * 64];
#pragma unroll
            for (int c8 = 0; c8 < 16; c8++) {
                ulonglong2 w = wr[c8];
                fma2(acc[2 * c8], hv, w.x);
                fma2(acc[2 * c8 + 1], hv, w.y);
            }
        }
    }
    float hp[64];
#pragma unroll
    for (int i = 0; i < 32; i++) {
        float2 f = unpack2(acc[i]);
        hp[2 * i] = f.x; hp[2 * i + 1] = f.y;
    }
    float as = 0.f, ad = 0.f;
#pragma unroll
    for (int c = 0; c < 64; c++) {
        as = fmaf(hp[c], sAs[c], as);
        ad = fmaf(hp[c], sAd[c], ad);
    }
    g_as2[node] = as;
    g_ad2[node] = ad;
    float es = __expf(lrelu(as + ad, 0.2f));
    g_asum2[node] = es;
#pragma unroll
    for (int q = 0; q < 8; q++) {
        int c = q * 8;
        uint4 u = make_uint4(h2bits(hp[c], hp[c + 1]), h2bits(hp[c + 2], hp[c + 3]),
                             h2bits(hp[c + 4], hp[c + 5]), h2bits(hp[c + 6], hp[c + 7]));
        *(uint4*)&g_hp2h[node * 32 + q * 4] = u;
    }
    // NOTE: no g_out2 seed store — msg2 self-seeds from g_hp2h * es
}

// ==================== kernel: gat2 gather (warp/node, R9 pipelined) ==========
__global__ void k_msg2(int n) {
    int warp = (blockIdx.x * blockDim.x + threadIdx.x) >> 5;
    if (warp >= n) return;
    int node = warp;
    int lane = threadIdx.x & 31;
    int beg = g_offs[node], end = g_offs[node + 1];

    float ad2 = g_ad2[node];
    float es2 = g_asum2[node];
    float2 hpv = h2f2(g_hp2h[node * 32 + lane]);
    float2 acc = make_float2(hpv.x * es2, hpv.y * es2);
    float wsum = 0.f;

    int i = beg;
    int idx0 = i + lane;
    int2 ce = (idx0 < end) ? g_csr[idx0] : make_int2(0, 0);
    float asv = g_as2[ce.x];

    for (; i + 32 <= end; ) {
        int inext = i + 32;
        int2 ce_n = ce; float as_n = asv;
        if (inext < end) {
            int idn = inext + lane;
            ce_n = (idn < end) ? g_csr[idn] : make_int2(0, 0);
            as_n = g_as2[ce_n.x];
        }
        float w32 = __expf(lrelu(asv + ad2, 0.2f));
        wsum += w32;
#pragma unroll
        for (int kk = 0; kk < 4; kk++) {
            int ss[8];
#pragma unroll
            for (int k = 0; k < 8; k++) ss[k] = __shfl_sync(0xffffffffu, ce.x, kk * 8 + k);
            float2 vv[8];
#pragma unroll
            for (int k = 0; k < 8; k++) vv[k] = h2f2(g_hp2h[ss[k] * 32 + lane]);
#pragma unroll
            for (int k = 0; k < 8; k++) {
                float wl = __shfl_sync(0xffffffffu, w32, kk * 8 + k);
                acc.x = fmaf(wl, vv[k].x, acc.x);
                acc.y = fmaf(wl, vv[k].y, acc.y);
            }
        }
        i = inext;
        ce = ce_n; asv = as_n;
    }
    if (i < end) {
        float w32 = (i + lane < end) ? __expf(lrelu(asv + ad2, 0.2f)) : 0.f;
        wsum += w32;
#pragma unroll
        for (int kk = 0; kk < 4; kk++) {
            if (i + kk * 8 >= end) break;
            int ss[8];
#pragma unroll
            for (int k = 0; k < 8; k++) ss[k] = __shfl_sync(0xffffffffu, ce.x, kk * 8 + k);
            float2 vv[8];
#pragma unroll
            for (int k = 0; k < 8; k++) vv[k] = h2f2(g_hp2h[ss[k] * 32 + lane]);
#pragma unroll
            for (int k = 0; k < 8; k++) {
                float wl = __shfl_sync(0xffffffffu, w32, kk * 8 + k);
                acc.x = fmaf(wl, vv[k].x, acc.x);
                acc.y = fmaf(wl, vv[k].y, acc.y);
            }
        }
    }
    *(float2*)&g_out2[node * 64 + lane * 2] = acc;
    wsum += __shfl_xor_sync(0xffffffffu, wsum, 16);
    wsum += __shfl_xor_sync(0xffffffffu, wsum, 8);
    wsum += __shfl_xor_sync(0xffffffffu, wsum, 4);
    wsum += __shfl_xor_sync(0xffffffffu, wsum, 2);
    wsum += __shfl_xor_sync(0xffffffffu, wsum, 1);
    if (lane == 0) g_asum2[node] += wsum;
}

// ==================== kernel: finish gat2 + EA/EB + node head (FFMA2) ========
__global__ void k_fin2_heads(const float* __restrict__ g2b,
                             const float* __restrict__ eoW1, const float* __restrict__ eob1,
                             const float* __restrict__ noW1, const float* __restrict__ nob1,
                             const float* __restrict__ noW2, const float* __restrict__ nob2,
                             float* __restrict__ out, int n, int e) {
    __shared__ __align__(16) float sWa[64 * 64];
    __shared__ __align__(16) float sWb[64 * 64];
    __shared__ __align__(16) float sWn[64 * 64];
    __shared__ __align__(16) float sB[64], sB1[64], sBn[64], sW2[128];
    for (int i = threadIdx.x; i < 4096; i += blockDim.x) {
        sWa[i] = eoW1[i];
        sWb[i] = eoW1[4096 + i];
        sWn[i] = noW1[i];
    }
    if (threadIdx.x < 64) {
        sB[threadIdx.x]  = g2b[threadIdx.x];
        sB1[threadIdx.x] = eob1[threadIdx.x];
        sBn[threadIdx.x] = nob1[threadIdx.x];
    }
    if (threadIdx.x < 128) sW2[threadIdx.x] = noW2[threadIdx.x];
    __syncthreads();
    int node = blockIdx.x * blockDim.x + threadIdx.x;
    if (node >= n) return;

    float inv = 1.0f / g_asum2[node];
    float h2[64];
#pragma unroll
    for (int c4 = 0; c4 < 16; c4++) {
        float4 o = *(const float4*)&g_out2[node * 64 + c4 * 4];
        h2[c4 * 4]     = o.x * inv + sB[c4 * 4];
        h2[c4 * 4 + 1] = o.y * inv + sB[c4 * 4 + 1];
        h2[c4 * 4 + 2] = o.z * inv + sB[c4 * 4 + 2];
        h2[c4 * 4 + 3] = o.w * inv + sB[c4 * 4 + 3];
    }

    ull acc[32];
    // ---- EA = h2 @ Wa + b1 (fp16 store) ----
#pragma unroll
    for (int i = 0; i < 32; i++) acc[i] = 0ULL;
#pragma unroll 4
    for (int k = 0; k < 64; k++) {
        ull hv = pack2(h2[k]);
        const ulonglong2* wr = (const ulonglong2*)&sWa[k * 64];
#pragma unroll
        for (int c8 = 0; c8 < 16; c8++) {
            ulonglong2 w = wr[c8];
            fma2(acc[2 * c8], hv, w.x);
            fma2(acc[2 * c8 + 1], hv, w.y);
        }
    }
#pragma unroll
    for (int q = 0; q < 8; q++) {
        float2 f0 = unpack2(acc[q * 4]),     f1 = unpack2(acc[q * 4 + 1]);
        float2 f2 = unpack2(acc[q * 4 + 2]), f3 = unpack2(acc[q * 4 + 3]);
        int c = q * 8;
        uint4 u = make_uint4(h2bits(f0.x + sB1[c], f0.y + sB1[c + 1]),
                             h2bits(f1.x + sB1[c + 2], f1.y + sB1[c + 3]),
                             h2bits(f2.x + sB1[c + 4], f2.y + sB1[c + 5]),
                             h2bits(f3.x + sB1[c + 6], f3.y + sB1[c + 7]));
        *(uint4*)&g_EAh[node * 32 + q * 4] = u;
    }
    // ---- EB = h2 @ Wb (fp32) ----
#pragma unroll
    for (int i = 0; i < 32; i++) acc[i] = 0ULL;
#pragma unroll 4
    for (int k = 0; k < 64; k++) {
        ull hv = pack2(h2[k]);
        const ulonglong2* wr = (const ulonglong2*)&sWb[k * 64];
#pragma unroll
        for (int c8 = 0; c8 < 16; c8++) {
            ulonglong2 w = wr[c8];
            fma2(acc[2 * c8], hv, w.x);
            fma2(acc[2 * c8 + 1], hv, w.y);
        }
    }
#pragma unroll
    for (int q = 0; q < 16; q++) {
        float2 f0 = unpack2(acc[q * 2]), f1 = unpack2(acc[q * 2 + 1]);
        *(float4*)&g_EB[node * 64 + q * 4] = make_float4(f0.x, f0.y, f1.x, f1.y);
    }
    // ---- node head ----
#pragma unroll
    for (int i = 0; i < 32; i++) acc[i] = 0ULL;
#pragma unroll 4
    for (int k = 0; k < 64; k++) {
        ull hv = pack2(h2[k]);
        const ulonglong2* wr = (const ulonglong2*)&sWn[k * 64];
#pragma unroll
        for (int c8 = 0; c8 < 16; c8++) {
            ulonglong2 w = wr[c8];
            fma2(acc[2 * c8], hv, w.x);
            fma2(acc[2 * c8 + 1], hv, w.y);
        }
    }
    float p0 = 0.f, p1 = 0.f;
#pragma unroll
    for (int i = 0; i < 32; i++) {
        float2 f = unpack2(acc[i]);
        float t0 = lrelu(f.x + sBn[2 * i], 0.01f);
        float t1 = lrelu(f.y + sBn[2 * i + 1], 0.01f);
        p0 = fmaf(t0, sW2[4 * i],     fmaf(t1, sW2[4 * i + 2], p0));
        p1 = fmaf(t0, sW2[4 * i + 1], fmaf(t1, sW2[4 * i + 3], p1));
    }
    out[e + node * 2]     = tanha(p0 + nob2[0]);
    out[e + node * 2 + 1] = tanha(p1 + nob2[1]);
}

// ==================== kernel: edge head (warp/node, R9 shape) ================
__global__ void k_edgehead(const float* __restrict__ eattr,
                           const float* __restrict__ eoW1,
                           const float* __restrict__ eoW2, const float* __restrict__ eob2,
                           float* __restrict__ out, int n) {
    int warp = (blockIdx.x * blockDim.x + threadIdx.x) >> 5;
    if (warp >= n) return;
    int node = warp;
    int lane = threadIdx.x & 31;
    int beg = g_offs[node], end = g_offs[node + 1];
    if (beg == end) return;

    float2 w128 = *(const float2*)&eoW1[128 * 64 + lane * 2];
    float2 w129 = *(const float2*)&eoW1[129 * 64 + lane * 2];
    float2 w2   = *(const float2*)&eoW2[lane * 2];
    float  b2   = eob2[0];
    float2 eb   = *(const float2*)&g_EB[node * 64 + lane * 2];

    int i = beg;
    int idx0 = i + lane;
    int2 ce = (idx0 < end) ? g_csr[idx0] : make_int2(0, 0);
    float2 ea = *(const float2*)&eattr[ce.y * 2];

    for (; i + 32 <= end; ) {
        int inext = i + 32;
        int2 ce_n = ce; float2 ea_n = ea;
        if (inext < end) {
            int idn = inext + lane;
            ce_n = (idn < end) ? g_csr[idn] : make_int2(0, 0);
            ea_n = *(const float2*)&eattr[ce_n.y * 2];
        }
#pragma unroll
        for (int kk = 0; kk < 4; kk++) {
            int ss[8], ei[8];
            float ex[8], ey[8];
#pragma unroll
            for (int k = 0; k < 8; k++) {
                ss[k] = __shfl_sync(0xffffffffu, ce.x, kk * 8 + k);
                ei[k] = __shfl_sync(0xffffffffu, ce.y, kk * 8 + k);
                ex[k] = __shfl_sync(0xffffffffu, ea.x, kk * 8 + k);
                ey[k] = __shfl_sync(0xffffffffu, ea.y, kk * 8 + k);
            }
            float2 va[8];
#pragma unroll
            for (int k = 0; k < 8; k++) va[k] = h2f2(g_EAh[ss[k] * 32 + lane]);
            float p[8];
#pragma unroll
            for (int k = 0; k < 8; k++) {
                float pre0 = va[k].x + eb.x + ex[k] * w128.x + ey[k] * w129.x;
                float pre1 = va[k].y + eb.y + ex[k] * w128.y + ey[k] * w129.y;
                p[k] = lrelu(pre0, 0.01f) * w2.x + lrelu(pre1, 0.01f) * w2.y;
            }
#pragma unroll
            for (int k = 0; k < 8; k++) {
                p[k] += __shfl_xor_sync(0xffffffffu, p[k], 16);
                p[k] += __shfl_xor_sync(0xffffffffu, p[k], 8);
                p[k] += __shfl_xor_sync(0xffffffffu, p[k], 4);
                p[k] += __shfl_xor_sync(0xffffffffu, p[k], 2);
                p[k] += __shfl_xor_sync(0xffffffffu, p[k], 1);
            }
            if (lane == 0) {
#pragma unroll
                for (int k = 0; k < 8; k++) out[ei[k]] = tanha(p[k] + b2);
            }
        }
        i = inext;
        ce = ce_n; ea = ea_n;
    }
    if (i < end) {
#pragma unroll
        for (int kk = 0; kk < 4; kk++) {
            if (i + kk * 8 >= end) break;
            int ss[8], ei[8];
            float ex[8], ey[8];
#pragma unroll
            for (int k = 0; k < 8; k++) {
                ss[k] = __shfl_sync(0xffffffffu, ce.x, kk * 8 + k);
                ei[k] = __shfl_sync(0xffffffffu, ce.y, kk * 8 + k);
                ex[k] = __shfl_sync(0xffffffffu, ea.x, kk * 8 + k);
                ey[k] = __shfl_sync(0xffffffffu, ea.y, kk * 8 + k);
            }
            float2 va[8];
#pragma unroll
            for (int k = 0; k < 8; k++) va[k] = h2f2(g_EAh[ss[k] * 32 + lane]);
            float p[8];
#pragma unroll
            for (int k = 0; k < 8; k++) {
                float pre0 = va[k].x + eb.x + ex[k] * w128.x + ey[k] * w129.x;
                float pre1 = va[k].y + eb.y + ex[k] * w128.y + ey[k] * w129.y;
                p[k] = lrelu(pre0, 0.01f) * w2.x + lrelu(pre1, 0.01f) * w2.y;
            }
#pragma unroll
            for (int k = 0; k < 8; k++) {
                p[k] += __shfl_xor_sync(0xffffffffu, p[k], 16);
                p[k] += __shfl_xor_sync(0xffffffffu, p[k], 8);
                p[k] += __shfl_xor_sync(0xffffffffu, p[k], 4);
                p[k] += __shfl_xor_sync(0xffffffffu, p[k], 2);
                p[k] += __shfl_xor_sync(0xffffffffu, p[k], 1);
            }
#pragma unroll
            for (int k = 0; k < 8; k++)
                if (lane == 0 && (i + kk * 8 + k) < end) out[ei[k]] = tanha(p[k] + b2);
        }
    }
}

// ==================== launch ==================================================
extern "C" void kernel_launch(void* const* d_in, const int* in_sizes, int n_in,
                              void* d_out, int out_size) {
    const float* x      = (const float*)d_in[0];
    const int*   eidx   = (const int*)d_in[1];
    const float* eattr  = (const float*)d_in[2];
    const float* encW   = (const float*)d_in[3];
    const float* encb   = (const float*)d_in[4];
    const float* g1W    = (const float*)d_in[5];
    const float* g1as   = (const float*)d_in[6];
    const float* g1ad   = (const float*)d_in[7];
    const float* g1b    = (const float*)d_in[8];
    const float* g2W    = (const float*)d_in[9];
    const float* g2as   = (const float*)d_in[10];
    const float* g2ad   = (const float*)d_in[11];
    const float* g2b    = (const float*)d_in[12];
    const float* noW1   = (const float*)d_in[13];
    const float* nob1   = (const float*)d_in[14];
    const float* noW2   = (const float*)d_in[15];
    const float* nob2   = (const float*)d_in[16];
    const float* eoW1   = (const float*)d_in[17];
    const float* eob1   = (const float*)d_in[18];
    const float* eoW2   = (const float*)d_in[19];
    const float* eob2   = (const float*)d_in[20];
    float* out = (float*)d_out;

    int n = in_sizes[0] / 2;
    int e = in_sizes[1] / 2;
    const int* src = eidx;
    const int* dst = eidx + e;

    const int B = 256;
    int gn = (n + B - 1) / B;
    int ge = (e + B - 1) / B;
    int gw = (n * 32 + B - 1) / B;

    // CSR build (dst-sorted) — g_cnt zero on entry, re-zeroed inside k_scanwrite
    k_hist<<<ge, B>>>(dst, e);
    k_sumscan<<<1, 1024>>>(n);
    k_scanwrite<<<NCHUNK, 1024>>>(n);
    k_scatter<<<ge, B>>>(src, dst, e);

    // pipeline
    k_enc_gat1<<<gn, B>>>(x, encW, encb, g1W, g1as, g1ad, n);
    k_msg1<<<gw, B>>>(n);
    k_fin1_gat2<<<gn, B>>>(g1b, g2W, g2as, g2ad, n);
    k_msg2<<<gw, B>>>(n);
    k_fin2_heads<<<gn, B>>>(g2b, eoW1, eob1, noW1, nob1, noW2, nob2, out, n, e);
    k_edgehead<<<gw, B>>>(eattr, eoW1, eoW2, eob2, out, n);
}